// round 4
// baseline (speedup 1.0000x reference)
#include <cuda_runtime.h>
#include <cstdint>
#include <math.h>

#define NB 8
#define CC 256
#define TT 120
#define VVC 25
#define PP (NB*TT*VVC)   // 24000 points
#define TV (TT*VVC)      // 3000
#define HH 8
#define HD 32
#define LLN 125
#define EPSV 1e-5f

// Scratch (device globals; no allocation anywhere)
__device__ __align__(16) float g_qkv[PP*768];    // (p, 768) cols = h*96 + s*32 + d
__device__ __align__(16) float g_ao[PP*256];     // mean-over-W attention out, (p, h*32+d)
__device__ __align__(16) float g_inter[PP*256];  // bn1 output, point-major
__device__ __align__(16) float g_h1[PP*256];     // ffn mid, point-major

// ---------------------------------------------------------------------------
// cp.async helpers
// ---------------------------------------------------------------------------
__device__ __forceinline__ void cp16(float* dst, const float* src) {
    unsigned int d = (unsigned int)__cvta_generic_to_shared(dst);
    asm volatile("cp.async.cg.shared.global [%0], [%1], 16;\n" :: "r"(d), "l"(src));
}
__device__ __forceinline__ void cp4(float* dst, const float* src) {
    unsigned int d = (unsigned int)__cvta_generic_to_shared(dst);
    asm volatile("cp.async.ca.shared.global [%0], [%1], 4;\n" :: "r"(d), "l"(src));
}
#define CP_COMMIT() asm volatile("cp.async.commit_group;\n" ::: "memory")
#define CP_WAIT1()  asm volatile("cp.async.wait_group 1;\n" ::: "memory")
#define CP_WAIT0()  asm volatile("cp.async.wait_group 0;\n" ::: "memory")

// Shared memory sizes (floats)
#define ASTR 36
#define A_TILE (64*ASTR)          // 2304
#define WSTR_X 260
#define W_TILE_X (32*WSTR_X)      // 8320
#define WSTR_Y 36
#define W_TILE_Y (256*WSTR_Y)     // 9216
#define SMEM_X_FLOATS (2*A_TILE + 2*W_TILE_X)      // 21248
#define SMEM_Y_FLOATS (2*A_TILE + 2*W_TILE_Y)      // 23040
#define SMEM_X_BYTES (SMEM_X_FLOATS*4)             // 84992
#define SMEM_Y_BYTES (SMEM_Y_FLOATS*4)             // 92160
#define STGSTR 260                                  // stage stride [pl][j]

// ---------------------------------------------------------------------------
// 64-point x 256-col GEMM, K=256, 512 threads, 8x4 microtile, fused epilogues.
// MODE 0: qkv : A = x (NCHW gather), W=(in,out) ld=768 -> g_qkv   (variant X)
// MODE 1: proj: A = g_ao, W=w_out (in,out), +b_out +x bn1 -> g_inter (X)
// MODE 2: ffn1: A = g_inter, W=ffn_w1 (out,in), mish bn -> g_h1    (variant Y)
// MODE 3: ffn2: A = g_h1, W=ffn_w2 (out,in), +g_inter bn2 -> out   (Y)
// Variant X: thread cols j = cg*4+jj (contiguous 4).
// Variant Y: thread cols j = cg + jj*64 (strided) — W copied untransposed.
// Modes 1/3 stage the NCHW-side tensor through smem for coalescing.
// ---------------------------------------------------------------------------
template<int MODE>
__global__ __launch_bounds__(512)
void gemm_kernel(const float* __restrict__ Aext, const float* __restrict__ Wm,
                 const float* __restrict__ bias, const float* __restrict__ res,
                 const float* __restrict__ bg, const float* __restrict__ bb,
                 const float* __restrict__ bm, const float* __restrict__ bv,
                 float* __restrict__ outp)
{
    extern __shared__ float sm[];
    float* A_s = sm;                      // [2][A_TILE]
    float* W_s = sm + 2*A_TILE;           // [2][W_TILE_X or W_TILE_Y]

    const int tid = threadIdx.x;
    const int cg = tid & 63;              // 64 col-groups
    const int pg = tid >> 6;              // 8 point-groups * 8 points
    const int p0 = blockIdx.x * 64;
    const int jb = (MODE == 0) ? (int)blockIdx.y * 256 : 0;

    const float* A;
    if constexpr (MODE == 0) A = Aext;
    else if constexpr (MODE == 1) A = g_ao;
    else if constexpr (MODE == 2) A = g_inter;
    else A = g_h1;

    float acc[8][4];
    #pragma unroll
    for (int i = 0; i < 8; ++i)
        #pragma unroll
        for (int j = 0; j < 4; ++j) acc[i][j] = 0.f;

    // ---- async tile loader ----
    auto load_tile = [&](int kt, int buf) {
        const int c0 = kt * 32;
        float* Ab = A_s + buf * A_TILE;
        if constexpr (MODE == 0) {
            #pragma unroll
            for (int it = 0; it < 4; ++it) {
                int lin = it * 512 + tid;          // 2048 scalars
                int pl = lin & 63, cl = lin >> 6;
                int p = p0 + pl;
                int n = p / TV, r = p - n * TV;
                cp4(&Ab[pl*ASTR + cl], &Aext[(n*CC + c0 + cl)*TV + r]);
            }
        } else {
            int pl = tid >> 3, f = tid & 7;        // 512 float4
            cp16(&Ab[pl*ASTR + f*4], &A[(p0 + pl)*256 + c0 + f*4]);
        }
        if constexpr (MODE == 0 || MODE == 1) {
            float* Wb = W_s + buf * W_TILE_X;
            const int ldw = (MODE == 0) ? 768 : 256;
            #pragma unroll
            for (int it = 0; it < 4; ++it) {
                int lin = it * 512 + tid;          // 2048 float4 = 32 rows x 64
                int cl = lin >> 6, f = lin & 63;
                cp16(&Wb[cl*WSTR_X + f*4], &Wm[(c0 + cl)*ldw + jb + f*4]);
            }
        } else {
            float* Wb = W_s + buf * W_TILE_Y;
            #pragma unroll
            for (int it = 0; it < 4; ++it) {
                int lin = it * 512 + tid;          // 2048 float4 = 256 rows x 8
                int j = lin >> 3, f = lin & 7;
                cp16(&Wb[j*WSTR_Y + f*4], &Wm[j*256 + c0 + f*4]);
            }
        }
    };

    load_tile(0, 0);
    CP_COMMIT();

    int buf = 0;
    for (int kt = 0; kt < 8; ++kt) {
        if (kt < 7) { load_tile(kt + 1, buf ^ 1); CP_COMMIT(); CP_WAIT1(); }
        else        { CP_WAIT0(); }
        __syncthreads();

        const float* Ab = A_s + buf * A_TILE;
        if constexpr (MODE == 0 || MODE == 1) {
            const float* Wb = W_s + buf * W_TILE_X;
            #pragma unroll
            for (int c4 = 0; c4 < 8; ++c4) {
                float4 a4[8];
                #pragma unroll
                for (int i = 0; i < 8; ++i)
                    a4[i] = *(const float4*)&Ab[(pg*8 + i)*ASTR + c4*4];
                #pragma unroll
                for (int cc = 0; cc < 4; ++cc) {
                    float4 w = *(const float4*)&Wb[(c4*4 + cc)*WSTR_X + cg*4];
                    #pragma unroll
                    for (int i = 0; i < 8; ++i) {
                        float av = (cc == 0) ? a4[i].x : (cc == 1) ? a4[i].y
                                 : (cc == 2) ? a4[i].z : a4[i].w;
                        acc[i][0] = fmaf(av, w.x, acc[i][0]);
                        acc[i][1] = fmaf(av, w.y, acc[i][1]);
                        acc[i][2] = fmaf(av, w.z, acc[i][2]);
                        acc[i][3] = fmaf(av, w.w, acc[i][3]);
                    }
                }
            }
        } else {
            const float* Wb = W_s + buf * W_TILE_Y;
            #pragma unroll
            for (int c4 = 0; c4 < 8; ++c4) {
                float4 a4[8];
                #pragma unroll
                for (int i = 0; i < 8; ++i)
                    a4[i] = *(const float4*)&Ab[(pg*8 + i)*ASTR + c4*4];
                float4 w4[4];
                #pragma unroll
                for (int j = 0; j < 4; ++j)
                    w4[j] = *(const float4*)&Wb[(cg + j*64)*WSTR_Y + c4*4];
                #pragma unroll
                for (int i = 0; i < 8; ++i)
                    #pragma unroll
                    for (int j = 0; j < 4; ++j) {
                        acc[i][j] = fmaf(a4[i].x, w4[j].x, acc[i][j]);
                        acc[i][j] = fmaf(a4[i].y, w4[j].y, acc[i][j]);
                        acc[i][j] = fmaf(a4[i].z, w4[j].z, acc[i][j]);
                        acc[i][j] = fmaf(a4[i].w, w4[j].w, acc[i][j]);
                    }
            }
        }
        __syncthreads();
        buf ^= 1;
    }

    // ---- epilogues ----
    if constexpr (MODE == 0) {
        #pragma unroll
        for (int i = 0; i < 8; ++i) {
            int p = p0 + pg*8 + i;
            *(float4*)&g_qkv[p*768 + jb + cg*4] = *(float4*)&acc[i][0];
        }
    } else if constexpr (MODE == 1) {
        // stage x residual through smem: [pl][j], coalesced global reads
        __syncthreads();
        #pragma unroll
        for (int it = 0; it < 32; ++it) {
            int lin = it * 512 + tid;
            int pl = lin & 63, j = lin >> 6;
            int p = p0 + pl;
            int n = p / TV, r = p - n * TV;
            sm[pl*STGSTR + j] = res[(n*CC + j)*TV + r];
        }
        __syncthreads();
        float sc[4], be[4], bo[4];
        #pragma unroll
        for (int jj = 0; jj < 4; ++jj) {
            int j = cg*4 + jj;
            sc[jj] = rsqrtf(bv[j] + EPSV) * bg[j];
            be[jj] = bb[j] - bm[j]*sc[jj];
            bo[jj] = bias[j];
        }
        #pragma unroll
        for (int i = 0; i < 8; ++i) {
            int p = p0 + pg*8 + i;
            float4 xr = *(const float4*)&sm[(pg*8 + i)*STGSTR + cg*4];
            float vals[4];
            vals[0] = (acc[i][0] + bo[0] + xr.x)*sc[0] + be[0];
            vals[1] = (acc[i][1] + bo[1] + xr.y)*sc[1] + be[1];
            vals[2] = (acc[i][2] + bo[2] + xr.z)*sc[2] + be[2];
            vals[3] = (acc[i][3] + bo[3] + xr.w)*sc[3] + be[3];
            *(float4*)&g_inter[p*256 + cg*4] = *(float4*)&vals[0];
        }
    } else if constexpr (MODE == 2) {
        float sc[4], be[4];
        #pragma unroll
        for (int jj = 0; jj < 4; ++jj) {
            int j = cg + jj*64;
            sc[jj] = rsqrtf(bv[j] + EPSV) * bg[j];
            be[jj] = bb[j] - bm[j]*sc[jj];
        }
        #pragma unroll
        for (int i = 0; i < 8; ++i) {
            int p = p0 + pg*8 + i;
            #pragma unroll
            for (int jj = 0; jj < 4; ++jj) {
                float a = acc[i][jj];
                float sp = (a > 20.f) ? a : log1pf(__expf(a));
                float ms = a * tanhf(sp);
                g_h1[p*256 + cg + jj*64] = ms*sc[jj] + be[jj];
            }
        }
    } else {
        float sc[4], be[4];
        #pragma unroll
        for (int jj = 0; jj < 4; ++jj) {
            int j = cg + jj*64;
            sc[jj] = rsqrtf(bv[j] + EPSV) * bg[j];
            be[jj] = bb[j] - bm[j]*sc[jj];
        }
        __syncthreads();
        // compute final value, stage transposed [pl][j] (conflict-free writes)
        #pragma unroll
        for (int i = 0; i < 8; ++i) {
            int p = p0 + pg*8 + i;
            #pragma unroll
            for (int jj = 0; jj < 4; ++jj) {
                int j = cg + jj*64;
                float rv = g_inter[p*256 + j];                 // coalesced
                sm[(pg*8 + i)*STGSTR + j] = (acc[i][jj] + rv)*sc[jj] + be[jj];
            }
        }
        __syncthreads();
        // coalesced NCHW scatter
        #pragma unroll
        for (int it = 0; it < 32; ++it) {
            int lin = it * 512 + tid;
            int pl = lin & 63, j = lin >> 6;
            int p = p0 + pl;
            int n = p / TV, r = p - n * TV;
            outp[(n*CC + j)*TV + r] = sm[pl*STGSTR + j];
        }
    }
}

// ---------------------------------------------------------------------------
// Attention: one block per (n*T + t, head). Q/K gathered in two 16-d chunks
// (smem 101KB -> 2 CTAs/SM). S = Q K^T / 16 accumulated across chunks,
// padded parallel softmax, O = S V over all 128 (padded exp=0, padded v=0),
// O overlays S after a barrier, mean over window slots -> g_ao.
// ---------------------------------------------------------------------------
#define SM_S    0                       // S[l*132 + m]        128*132 = 16896
#define SM_K    16896                   // ks_t[dd*132 + m]    16*132  = 2112
#define SM_Q    19008                   // qs_t[dd*132 + m]    2112
#define SM_V    21120                   // vs[m*36 + d]        128*36  = 4608
#define SM_SUM  25728                   // sums[128]
#define SM_O    0                       // O_s[l*36 + d] overlays S (post-sync)
#define ATTN_SMEM_FLOATS 25856          // 103424 bytes

__global__ __launch_bounds__(256)
void attn_kernel()
{
    extern __shared__ float smA[];
    float* S    = smA + SM_S;
    float* ks_t = smA + SM_K;
    float* qs_t = smA + SM_Q;
    float* vs   = smA + SM_V;
    float* sums = smA + SM_SUM;
    float* O_s  = smA + SM_O;

    const int tid = threadIdx.x;
    const int bx = blockIdx.x, h = blockIdx.y;
    const int n = bx / TT, t = bx - n * TT;

    // gather V once (zero pad out-of-range times and rows 125..127)
    for (int lin = tid; lin < 4096; lin += 256) {
        int m = lin >> 5, d = lin & 31;
        float v = 0.f;
        if (m < LLN) {
            int w = m / VVC;
            int vv = m - w * VVC;
            int ti = t + w - 2;
            if (ti >= 0 && ti < TT)
                v = g_qkv[((size_t)((n*TT + ti)*VVC + vv))*768 + h*96 + 64 + d];
        }
        vs[m*36 + d] = v;
    }

    // S = Q K^T * (1/16): two 16-d chunks, acc persistent in registers
    const int ty = tid >> 4, tx = tid & 15;
    float acc[8][8];
    #pragma unroll
    for (int i = 0; i < 8; ++i)
        #pragma unroll
        for (int j = 0; j < 8; ++j) acc[i][j] = 0.f;

    #pragma unroll
    for (int dh = 0; dh < 2; ++dh) {
        // gather 16-d chunk of q and k
        for (int lin = tid; lin < 2048; lin += 256) {
            int m = lin >> 4, dd = lin & 15;
            float q = 0.f, k = 0.f;
            if (m < LLN) {
                int w = m / VVC;
                int vv = m - w * VVC;
                int ti = t + w - 2;
                if (ti >= 0 && ti < TT) {
                    const float* bp = &g_qkv[((size_t)((n*TT + ti)*VVC + vv))*768
                                             + h*96 + dh*16 + dd];
                    q = bp[0]; k = bp[32];
                }
            }
            qs_t[dd*132 + m] = q;
            ks_t[dd*132 + m] = k;
        }
        __syncthreads();
        #pragma unroll
        for (int dd = 0; dd < 16; ++dd) {
            float a[8], b[8];
            *(float4*)&a[0] = *(const float4*)&qs_t[dd*132 + ty*8];
            *(float4*)&a[4] = *(const float4*)&qs_t[dd*132 + ty*8 + 4];
            *(float4*)&b[0] = *(const float4*)&ks_t[dd*132 + tx*8];
            *(float4*)&b[4] = *(const float4*)&ks_t[dd*132 + tx*8 + 4];
            #pragma unroll
            for (int i = 0; i < 8; ++i)
                #pragma unroll
                for (int j = 0; j < 8; ++j)
                    acc[i][j] = fmaf(a[i], b[j], acc[i][j]);
        }
        __syncthreads();
    }
    #pragma unroll
    for (int i = 0; i < 8; ++i) {
        float tmp[8];
        #pragma unroll
        for (int j = 0; j < 8; ++j) tmp[j] = acc[i][j] * 0.0625f;
        if (tx == 15) { tmp[5] = -1e30f; tmp[6] = -1e30f; tmp[7] = -1e30f; }
        *(float4*)&S[(ty*8 + i)*132 + tx*8]     = *(float4*)&tmp[0];
        *(float4*)&S[(ty*8 + i)*132 + tx*8 + 4] = *(float4*)&tmp[4];
    }
    __syncthreads();

    // parallel softmax: one thread per row, float4 passes (conflict-free:
    // row stride 132 floats = 33 float4 -> perfect phase spread)
    if (tid < 128) {
        const int l = tid;
        float4* row = (float4*)&S[l*132];
        float mx = -1e30f;
        #pragma unroll
        for (int i = 0; i < 32; ++i) {
            float4 f = row[i];
            mx = fmaxf(mx, fmaxf(fmaxf(f.x, f.y), fmaxf(f.z, f.w)));
        }
        float s = 0.f;
        #pragma unroll
        for (int i = 0; i < 32; ++i) {
            float4 f = row[i];
            f.x = __expf(f.x - mx); f.y = __expf(f.y - mx);
            f.z = __expf(f.z - mx); f.w = __expf(f.w - mx);
            s += f.x + f.y + f.z + f.w;
            row[i] = f;
        }
        sums[l] = s;
    }
    __syncthreads();

    // O = S V over all 128 m, divide by sums; result kept in registers
    const int ty2 = tid >> 3, tx2 = tid & 7;
    float oacc[4][4];
    #pragma unroll
    for (int i = 0; i < 4; ++i)
        #pragma unroll
        for (int j = 0; j < 4; ++j) oacc[i][j] = 0.f;
    #pragma unroll 8
    for (int m = 0; m < 128; ++m) {
        float a[4], b[4];
        #pragma unroll
        for (int i = 0; i < 4; ++i) a[i] = S[(ty2*4 + i)*132 + m];
        *(float4*)&b[0] = *(const float4*)&vs[m*36 + tx2*4];
        #pragma unroll
        for (int i = 0; i < 4; ++i)
            #pragma unroll
            for (int j = 0; j < 4; ++j)
                oacc[i][j] = fmaf(a[i], b[j], oacc[i][j]);
    }
    __syncthreads();   // everyone done reading S before O overlays it
    #pragma unroll
    for (int i = 0; i < 4; ++i) {
        int l = ty2*4 + i;
        float rl = 1.f / sums[l];
        float tmp[4];
        #pragma unroll
        for (int j = 0; j < 4; ++j) tmp[j] = oacc[i][j] * rl;
        *(float4*)&O_s[l*36 + tx2*4] = *(float4*)&tmp[0];
    }
    __syncthreads();

    // mean over the 5 window slots -> g_ao
    for (int lin = tid; lin < 800; lin += 256) {
        int vv = lin >> 5, d = lin & 31;
        float s = 0.f;
        #pragma unroll
        for (int w = 0; w < 5; ++w) s += O_s[(w*VVC + vv)*36 + d];
        g_ao[((size_t)((n*TT + t)*VVC + vv))*256 + h*HD + d] = 0.2f * s;
    }
}

// ---------------------------------------------------------------------------
extern "C" void kernel_launch(void* const* d_in, const int* in_sizes, int n_in,
                              void* d_out, int out_size)
{
    const float* x      = (const float*)d_in[0];
    const float* w_qkv  = (const float*)d_in[1];
    const float* w_out  = (const float*)d_in[2];
    const float* b_out  = (const float*)d_in[3];
    const float* bn1_g  = (const float*)d_in[4];
    const float* bn1_b  = (const float*)d_in[5];
    const float* ffn_w1 = (const float*)d_in[6];
    const float* ffn_w2 = (const float*)d_in[7];
    const float* ffn_g  = (const float*)d_in[8];
    const float* ffn_b  = (const float*)d_in[9];
    const float* bn2_g  = (const float*)d_in[10];
    const float* bn2_b  = (const float*)d_in[11];
    const float* bn1_m  = (const float*)d_in[12];
    const float* bn1_v  = (const float*)d_in[13];
    const float* ffn_m  = (const float*)d_in[14];
    const float* ffn_v  = (const float*)d_in[15];
    const float* bn2_m  = (const float*)d_in[16];
    const float* bn2_v  = (const float*)d_in[17];
    float* out = (float*)d_out;

    static int attr_done = 0;
    if (!attr_done) {
        cudaFuncSetAttribute(attn_kernel,
            cudaFuncAttributeMaxDynamicSharedMemorySize, ATTN_SMEM_FLOATS * 4);
        cudaFuncSetAttribute(gemm_kernel<0>,
            cudaFuncAttributeMaxDynamicSharedMemorySize, SMEM_X_BYTES);
        cudaFuncSetAttribute(gemm_kernel<1>,
            cudaFuncAttributeMaxDynamicSharedMemorySize, SMEM_X_BYTES);
        cudaFuncSetAttribute(gemm_kernel<2>,
            cudaFuncAttributeMaxDynamicSharedMemorySize, SMEM_Y_BYTES);
        cudaFuncSetAttribute(gemm_kernel<3>,
            cudaFuncAttributeMaxDynamicSharedMemorySize, SMEM_Y_BYTES);
        attr_done = 1;
    }

    // K1: QKV projection (all 768 cols, 3 sections via grid.y)
    gemm_kernel<0><<<dim3(PP/64, 3), 512, SMEM_X_BYTES>>>(x, w_qkv,
        nullptr, nullptr, nullptr, nullptr, nullptr, nullptr, nullptr);

    // K2: attention + mean over window slots
    attn_kernel<<<dim3(NB*TT, HH), 256, ATTN_SMEM_FLOATS * 4>>>();

    // K3: out projection + b_out + x residual + bn1 -> g_inter
    gemm_kernel<1><<<PP/64, 512, SMEM_X_BYTES>>>(nullptr, w_out,
        b_out, x, bn1_g, bn1_b, bn1_m, bn1_v, nullptr);

    // K4: ffn1 + mish + bn(ffn) -> g_h1
    gemm_kernel<2><<<PP/64, 512, SMEM_Y_BYTES>>>(nullptr, ffn_w1,
        nullptr, nullptr, ffn_g, ffn_b, ffn_m, ffn_v, nullptr);

    // K5: ffn2 + residual(g_inter) + bn2 -> out (coalesced NCHW scatter)
    gemm_kernel<3><<<PP/64, 512, SMEM_Y_BYTES>>>(nullptr, ffn_w2,
        nullptr, nullptr, bn2_g, bn2_b, bn2_m, bn2_v, out);
}

// round 5
// speedup vs baseline: 1.2992x; 1.2992x over previous
#include <cuda_runtime.h>
#include <cstdint>
#include <math.h>

#define NB 8
#define CC 256
#define TT 120
#define VVC 25
#define PP (NB*TT*VVC)   // 24000 points
#define TV (TT*VVC)      // 3000
#define HH 8
#define HD 32
#define LLN 125
#define EPSV 1e-5f

// Scratch (device globals; no allocation anywhere)
__device__ __align__(16) float g_qkv[PP*768];    // (p, 768) cols = h*96 + s*32 + d
__device__ __align__(16) float g_ao[PP*256];     // mean-over-W attention out, (p, h*32+d)
__device__ __align__(16) float g_inter[PP*256];  // bn1 output, point-major
__device__ __align__(16) float g_h1[PP*256];     // ffn mid, point-major

// ---------------------------------------------------------------------------
// cp.async helpers
// ---------------------------------------------------------------------------
__device__ __forceinline__ void cp16(float* dst, const float* src) {
    unsigned int d = (unsigned int)__cvta_generic_to_shared(dst);
    asm volatile("cp.async.cg.shared.global [%0], [%1], 16;\n" :: "r"(d), "l"(src));
}
__device__ __forceinline__ void cp4(float* dst, const float* src) {
    unsigned int d = (unsigned int)__cvta_generic_to_shared(dst);
    asm volatile("cp.async.ca.shared.global [%0], [%1], 4;\n" :: "r"(d), "l"(src));
}
#define CP_COMMIT() asm volatile("cp.async.commit_group;\n" ::: "memory")
#define CP_WAIT1()  asm volatile("cp.async.wait_group 1;\n" ::: "memory")
#define CP_WAIT0()  asm volatile("cp.async.wait_group 0;\n" ::: "memory")

// Shared memory sizes (floats)
#define ASTR 36
#define A_TILE (64*ASTR)          // 2304
#define WSTR_X 260
#define W_TILE_X (32*WSTR_X)      // 8320
#define WSTR_Y 36
#define W_TILE_Y (256*WSTR_Y)     // 9216
#define SMEM_X_BYTES ((2*A_TILE + 2*W_TILE_X)*4)   // 84992
#define SMEM_Y_BYTES ((2*A_TILE + 2*W_TILE_Y)*4)   // 92160
#define STGSTR 260                                  // stage stride [pl][j]

// ---------------------------------------------------------------------------
// 64-point x 256-col GEMM, K=256, 512 threads, 8x4 microtile, fused epilogues.
// MODE 0: qkv : A = x (NCHW gather), W=(in,out) ld=768 -> g_qkv   (variant X)
// MODE 1: proj: A = g_ao, W=w_out (in,out), +b_out +x bn1 -> g_inter (X)
// MODE 2: ffn1: A = g_inter, W=ffn_w1 (out,in), mish bn -> g_h1    (variant Y)
// MODE 3: ffn2: A = g_h1, W=ffn_w2 (out,in), +g_inter bn2 -> out   (Y)
// ---------------------------------------------------------------------------
template<int MODE>
__global__ __launch_bounds__(512)
void gemm_kernel(const float* __restrict__ Aext, const float* __restrict__ Wm,
                 const float* __restrict__ bias, const float* __restrict__ res,
                 const float* __restrict__ bg, const float* __restrict__ bb,
                 const float* __restrict__ bm, const float* __restrict__ bv,
                 float* __restrict__ outp)
{
    extern __shared__ float sm[];
    float* A_s = sm;                      // [2][A_TILE]
    float* W_s = sm + 2*A_TILE;           // [2][W_TILE_X or W_TILE_Y]

    const int tid = threadIdx.x;
    const int cg = tid & 63;              // 64 col-groups
    const int pg = tid >> 6;              // 8 point-groups * 8 points
    const int p0 = blockIdx.x * 64;
    const int jb = (MODE == 0) ? (int)blockIdx.y * 256 : 0;

    const float* A;
    if constexpr (MODE == 0) A = Aext;
    else if constexpr (MODE == 1) A = g_ao;
    else if constexpr (MODE == 2) A = g_inter;
    else A = g_h1;

    float acc[8][4];
    #pragma unroll
    for (int i = 0; i < 8; ++i)
        #pragma unroll
        for (int j = 0; j < 4; ++j) acc[i][j] = 0.f;

    auto load_tile = [&](int kt, int buf) {
        const int c0 = kt * 32;
        float* Ab = A_s + buf * A_TILE;
        if constexpr (MODE == 0) {
            #pragma unroll
            for (int it = 0; it < 4; ++it) {
                int lin = it * 512 + tid;          // 2048 scalars
                int pl = lin & 63, cl = lin >> 6;
                int p = p0 + pl;
                int n = p / TV, r = p - n * TV;
                cp4(&Ab[pl*ASTR + cl], &Aext[(n*CC + c0 + cl)*TV + r]);
            }
        } else {
            int pl = tid >> 3, f = tid & 7;        // 512 float4
            cp16(&Ab[pl*ASTR + f*4], &A[(p0 + pl)*256 + c0 + f*4]);
        }
        if constexpr (MODE == 0 || MODE == 1) {
            float* Wb = W_s + buf * W_TILE_X;
            const int ldw = (MODE == 0) ? 768 : 256;
            #pragma unroll
            for (int it = 0; it < 4; ++it) {
                int lin = it * 512 + tid;          // 2048 float4 = 32 rows x 64
                int cl = lin >> 6, f = lin & 63;
                cp16(&Wb[cl*WSTR_X + f*4], &Wm[(c0 + cl)*ldw + jb + f*4]);
            }
        } else {
            float* Wb = W_s + buf * W_TILE_Y;
            #pragma unroll
            for (int it = 0; it < 4; ++it) {
                int lin = it * 512 + tid;          // 2048 float4 = 256 rows x 8
                int j = lin >> 3, f = lin & 7;
                cp16(&Wb[j*WSTR_Y + f*4], &Wm[j*256 + c0 + f*4]);
            }
        }
    };

    load_tile(0, 0);
    CP_COMMIT();

    int buf = 0;
    for (int kt = 0; kt < 8; ++kt) {
        if (kt < 7) { load_tile(kt + 1, buf ^ 1); CP_COMMIT(); CP_WAIT1(); }
        else        { CP_WAIT0(); }
        __syncthreads();

        const float* Ab = A_s + buf * A_TILE;
        if constexpr (MODE == 0 || MODE == 1) {
            const float* Wb = W_s + buf * W_TILE_X;
            #pragma unroll
            for (int c4 = 0; c4 < 8; ++c4) {
                float4 a4[8];
                #pragma unroll
                for (int i = 0; i < 8; ++i)
                    a4[i] = *(const float4*)&Ab[(pg*8 + i)*ASTR + c4*4];
                #pragma unroll
                for (int cc = 0; cc < 4; ++cc) {
                    float4 w = *(const float4*)&Wb[(c4*4 + cc)*WSTR_X + cg*4];
                    #pragma unroll
                    for (int i = 0; i < 8; ++i) {
                        float av = (cc == 0) ? a4[i].x : (cc == 1) ? a4[i].y
                                 : (cc == 2) ? a4[i].z : a4[i].w;
                        acc[i][0] = fmaf(av, w.x, acc[i][0]);
                        acc[i][1] = fmaf(av, w.y, acc[i][1]);
                        acc[i][2] = fmaf(av, w.z, acc[i][2]);
                        acc[i][3] = fmaf(av, w.w, acc[i][3]);
                    }
                }
            }
        } else {
            const float* Wb = W_s + buf * W_TILE_Y;
            #pragma unroll
            for (int c4 = 0; c4 < 8; ++c4) {
                float4 a4[8];
                #pragma unroll
                for (int i = 0; i < 8; ++i)
                    a4[i] = *(const float4*)&Ab[(pg*8 + i)*ASTR + c4*4];
                float4 w4[4];
                #pragma unroll
                for (int j = 0; j < 4; ++j)
                    w4[j] = *(const float4*)&Wb[(cg + j*64)*WSTR_Y + c4*4];
                #pragma unroll
                for (int i = 0; i < 8; ++i)
                    #pragma unroll
                    for (int j = 0; j < 4; ++j) {
                        acc[i][j] = fmaf(a4[i].x, w4[j].x, acc[i][j]);
                        acc[i][j] = fmaf(a4[i].y, w4[j].y, acc[i][j]);
                        acc[i][j] = fmaf(a4[i].z, w4[j].z, acc[i][j]);
                        acc[i][j] = fmaf(a4[i].w, w4[j].w, acc[i][j]);
                    }
            }
        }
        __syncthreads();
        buf ^= 1;
    }

    // ---- epilogues ----
    if constexpr (MODE == 0) {
        #pragma unroll
        for (int i = 0; i < 8; ++i) {
            int p = p0 + pg*8 + i;
            *(float4*)&g_qkv[p*768 + jb + cg*4] = *(float4*)&acc[i][0];
        }
    } else if constexpr (MODE == 1) {
        __syncthreads();
        #pragma unroll
        for (int it = 0; it < 32; ++it) {
            int lin = it * 512 + tid;
            int pl = lin & 63, j = lin >> 6;
            int p = p0 + pl;
            int n = p / TV, r = p - n * TV;
            sm[pl*STGSTR + j] = res[(n*CC + j)*TV + r];
        }
        __syncthreads();
        float sc[4], be[4], bo[4];
        #pragma unroll
        for (int jj = 0; jj < 4; ++jj) {
            int j = cg*4 + jj;
            sc[jj] = rsqrtf(bv[j] + EPSV) * bg[j];
            be[jj] = bb[j] - bm[j]*sc[jj];
            bo[jj] = bias[j];
        }
        #pragma unroll
        for (int i = 0; i < 8; ++i) {
            int p = p0 + pg*8 + i;
            float4 xr = *(const float4*)&sm[(pg*8 + i)*STGSTR + cg*4];
            float vals[4];
            vals[0] = (acc[i][0] + bo[0] + xr.x)*sc[0] + be[0];
            vals[1] = (acc[i][1] + bo[1] + xr.y)*sc[1] + be[1];
            vals[2] = (acc[i][2] + bo[2] + xr.z)*sc[2] + be[2];
            vals[3] = (acc[i][3] + bo[3] + xr.w)*sc[3] + be[3];
            *(float4*)&g_inter[p*256 + cg*4] = *(float4*)&vals[0];
        }
    } else if constexpr (MODE == 2) {
        float sc[4], be[4];
        #pragma unroll
        for (int jj = 0; jj < 4; ++jj) {
            int j = cg + jj*64;
            sc[jj] = rsqrtf(bv[j] + EPSV) * bg[j];
            be[jj] = bb[j] - bm[j]*sc[jj];
        }
        #pragma unroll
        for (int i = 0; i < 8; ++i) {
            int p = p0 + pg*8 + i;
            #pragma unroll
            for (int jj = 0; jj < 4; ++jj) {
                float a = acc[i][jj];
                float sp = (a > 20.f) ? a : log1pf(__expf(a));
                float ms = a * tanhf(sp);
                g_h1[p*256 + cg + jj*64] = ms*sc[jj] + be[jj];
            }
        }
    } else {
        float sc[4], be[4];
        #pragma unroll
        for (int jj = 0; jj < 4; ++jj) {
            int j = cg + jj*64;
            sc[jj] = rsqrtf(bv[j] + EPSV) * bg[j];
            be[jj] = bb[j] - bm[j]*sc[jj];
        }
        __syncthreads();
        #pragma unroll
        for (int i = 0; i < 8; ++i) {
            int p = p0 + pg*8 + i;
            #pragma unroll
            for (int jj = 0; jj < 4; ++jj) {
                int j = cg + jj*64;
                float rv = g_inter[p*256 + j];                 // coalesced
                sm[(pg*8 + i)*STGSTR + j] = (acc[i][jj] + rv)*sc[jj] + be[jj];
            }
        }
        __syncthreads();
        #pragma unroll
        for (int it = 0; it < 32; ++it) {
            int lin = it * 512 + tid;
            int pl = lin & 63, j = lin >> 6;
            int p = p0 + pl;
            int n = p / TV, r = p - n * TV;
            outp[(n*CC + j)*TV + r] = sm[pl*STGSTR + j];
        }
    }
}

// ---------------------------------------------------------------------------
// Attention v3: one block per (n*T + t, head), 2 CTAs/SM.
// Key algebra: mean_w(softmax_rows @ V) = (mean_w softmax_rows) @ V, so the
// SV GEMM shrinks 5x (25x128x32). Layout (floats):
//   S    [125][132] at 0       (rows >=125 never written)
//   K^T  [32][132]  at 16500   (V[128][32] overlays it after QK; sums at tail)
//   Q^T  [32][132]  at 20724   (S-bar [25][132] overlays it after QK)
// Total 24948 floats = 99792 B -> 2 CTAs/SM; launch_bounds(256,2) caps regs.
// ---------------------------------------------------------------------------
#define AT_S    0
#define AT_K    16500
#define AT_Q    20724
#define AT_V    AT_K                     // 128*32 = 4096 <= 4224
#define AT_SUM  (AT_K + 4096)            // 125 floats in K-region tail
#define AT_SB   AT_Q                     // 25*132 = 3300 <= 4224
#define ATTN_SMEM_FLOATS 24948           // 99792 bytes

__global__ __launch_bounds__(256, 2)
void attn_kernel()
{
    extern __shared__ float smA[];
    float* S    = smA + AT_S;
    float* ks_t = smA + AT_K;
    float* qs_t = smA + AT_Q;
    float* vs   = smA + AT_V;
    float* sums = smA + AT_SUM;
    float* Sb   = smA + AT_SB;

    const int tid = threadIdx.x;
    const int bx = blockIdx.x, h = blockIdx.y;
    const int n = bx / TT, t = bx - n * TT;

    // ---- phase 1: gather Q^T, K^T (zero pad OOR times; m rows 125..127 = 0)
    for (int lin = tid; lin < 4096; lin += 256) {
        int m = lin >> 5, d = lin & 31;
        float q = 0.f, k = 0.f;
        if (m < LLN) {
            int w = m / VVC;
            int vv = m - w * VVC;
            int ti = t + w - 2;
            if (ti >= 0 && ti < TT) {
                const float* bp = &g_qkv[((size_t)((n*TT + ti)*VVC + vv))*768 + h*96 + d];
                q = bp[0]; k = bp[32];
            }
        }
        qs_t[d*132 + m] = q;
        ks_t[d*132 + m] = k;
    }
    __syncthreads();

    // ---- phase 2: S = Q K^T / 16 (rows l < 125 only; cols 125..127 = -inf)
    {
        const int ty = tid >> 4, tx = tid & 15;
        float acc[8][8];
        #pragma unroll
        for (int i = 0; i < 8; ++i)
            #pragma unroll
            for (int j = 0; j < 8; ++j) acc[i][j] = 0.f;
        #pragma unroll 8
        for (int d = 0; d < 32; ++d) {
            float a[8], b[8];
            *(float4*)&a[0] = *(const float4*)&qs_t[d*132 + ty*8];
            *(float4*)&a[4] = *(const float4*)&qs_t[d*132 + ty*8 + 4];
            *(float4*)&b[0] = *(const float4*)&ks_t[d*132 + tx*8];
            *(float4*)&b[4] = *(const float4*)&ks_t[d*132 + tx*8 + 4];
            #pragma unroll
            for (int i = 0; i < 8; ++i)
                #pragma unroll
                for (int j = 0; j < 8; ++j)
                    acc[i][j] = fmaf(a[i], b[j], acc[i][j]);
        }
        #pragma unroll
        for (int i = 0; i < 8; ++i) {
            int l = ty*8 + i;
            if (l < LLN) {
                float tmp[8];
                #pragma unroll
                for (int j = 0; j < 8; ++j) tmp[j] = acc[i][j] * 0.0625f;
                if (tx == 15) { tmp[5] = -1e30f; tmp[6] = -1e30f; tmp[7] = -1e30f; }
                *(float4*)&S[l*132 + tx*8]     = *(float4*)&tmp[0];
                *(float4*)&S[l*132 + tx*8 + 4] = *(float4*)&tmp[4];
            }
        }
    }
    __syncthreads();

    // ---- phase 3a: gather V into K-region (K dead after QK)
    for (int lin = tid; lin < 4096; lin += 256) {
        int m = lin >> 5, d = lin & 31;
        float v = 0.f;
        if (m < LLN) {
            int w = m / VVC;
            int vv = m - w * VVC;
            int ti = t + w - 2;
            if (ti >= 0 && ti < TT)
                v = g_qkv[((size_t)((n*TT + ti)*VVC + vv))*768 + h*96 + 64 + d];
        }
        vs[m*32 + d] = v;
    }
    // ---- phase 3b: softmax rows (exp stored; sum deferred to the average)
    if (tid < LLN) {
        const int l = tid;
        float4* row = (float4*)&S[l*132];
        float mx = -1e30f;
        #pragma unroll
        for (int i = 0; i < 32; ++i) {
            float4 f = row[i];
            mx = fmaxf(mx, fmaxf(fmaxf(f.x, f.y), fmaxf(f.z, f.w)));
        }
        float s = 0.f;
        #pragma unroll
        for (int i = 0; i < 32; ++i) {
            float4 f = row[i];
            f.x = __expf(f.x - mx); f.y = __expf(f.y - mx);
            f.z = __expf(f.z - mx); f.w = __expf(f.w - mx);
            s += f.x + f.y + f.z + f.w;
            row[i] = f;
        }
        sums[l] = 0.2f / s;       // fold the 1/5 window mean in here
    }
    __syncthreads();

    // ---- phase 4: S-bar[v] = sum_w S[(w,v)] * (0.2/sum_w) into Q-region
    for (int task = tid; task < 25*32; task += 256) {
        int v = task >> 5, i4 = task & 31;
        float4 r = make_float4(0.f, 0.f, 0.f, 0.f);
        #pragma unroll
        for (int w = 0; w < 5; ++w) {
            int l = w*VVC + v;
            float rs = sums[l];
            float4 f = *(const float4*)&S[l*132 + i4*4];
            r.x = fmaf(f.x, rs, r.x); r.y = fmaf(f.y, rs, r.y);
            r.z = fmaf(f.z, rs, r.z); r.w = fmaf(f.w, rs, r.w);
        }
        *(float4*)&Sb[v*132 + i4*4] = r;
    }
    __syncthreads();

    // ---- phase 5: O = S-bar @ V (25 x 32), write g_ao
    if (tid < 200) {
        const int v = tid >> 3, g = tid & 7;
        float4 acc = make_float4(0.f, 0.f, 0.f, 0.f);
        #pragma unroll 8
        for (int m = 0; m < 128; ++m) {
            float a = Sb[v*132 + m];
            float4 b = *(const float4*)&vs[m*32 + g*4];
            acc.x = fmaf(a, b.x, acc.x); acc.y = fmaf(a, b.y, acc.y);
            acc.z = fmaf(a, b.z, acc.z); acc.w = fmaf(a, b.w, acc.w);
        }
        *(float4*)&g_ao[((size_t)((n*TT + t)*VVC + v))*256 + h*HD + g*4] = acc;
    }
}

// ---------------------------------------------------------------------------
extern "C" void kernel_launch(void* const* d_in, const int* in_sizes, int n_in,
                              void* d_out, int out_size)
{
    const float* x      = (const float*)d_in[0];
    const float* w_qkv  = (const float*)d_in[1];
    const float* w_out  = (const float*)d_in[2];
    const float* b_out  = (const float*)d_in[3];
    const float* bn1_g  = (const float*)d_in[4];
    const float* bn1_b  = (const float*)d_in[5];
    const float* ffn_w1 = (const float*)d_in[6];
    const float* ffn_w2 = (const float*)d_in[7];
    const float* ffn_g  = (const float*)d_in[8];
    const float* ffn_b  = (const float*)d_in[9];
    const float* bn2_g  = (const float*)d_in[10];
    const float* bn2_b  = (const float*)d_in[11];
    const float* bn1_m  = (const float*)d_in[12];
    const float* bn1_v  = (const float*)d_in[13];
    const float* ffn_m  = (const float*)d_in[14];
    const float* ffn_v  = (const float*)d_in[15];
    const float* bn2_m  = (const float*)d_in[16];
    const float* bn2_v  = (const float*)d_in[17];
    float* out = (float*)d_out;

    static int attr_done = 0;
    if (!attr_done) {
        cudaFuncSetAttribute(attn_kernel,
            cudaFuncAttributeMaxDynamicSharedMemorySize, ATTN_SMEM_FLOATS * 4);
        cudaFuncSetAttribute(gemm_kernel<0>,
            cudaFuncAttributeMaxDynamicSharedMemorySize, SMEM_X_BYTES);
        cudaFuncSetAttribute(gemm_kernel<1>,
            cudaFuncAttributeMaxDynamicSharedMemorySize, SMEM_X_BYTES);
        cudaFuncSetAttribute(gemm_kernel<2>,
            cudaFuncAttributeMaxDynamicSharedMemorySize, SMEM_Y_BYTES);
        cudaFuncSetAttribute(gemm_kernel<3>,
            cudaFuncAttributeMaxDynamicSharedMemorySize, SMEM_Y_BYTES);
        attr_done = 1;
    }

    // K1: QKV projection (all 768 cols, 3 sections via grid.y)
    gemm_kernel<0><<<dim3(PP/64, 3), 512, SMEM_X_BYTES>>>(x, w_qkv,
        nullptr, nullptr, nullptr, nullptr, nullptr, nullptr, nullptr);

    // K2: attention + mean over window slots
    attn_kernel<<<dim3(NB*TT, HH), 256, ATTN_SMEM_FLOATS * 4>>>();

    // K3: out projection + b_out + x residual + bn1 -> g_inter
    gemm_kernel<1><<<PP/64, 512, SMEM_X_BYTES>>>(nullptr, w_out,
        b_out, x, bn1_g, bn1_b, bn1_m, bn1_v, nullptr);

    // K4: ffn1 + mish + bn(ffn) -> g_h1
    gemm_kernel<2><<<PP/64, 512, SMEM_Y_BYTES>>>(nullptr, ffn_w1,
        nullptr, nullptr, ffn_g, ffn_b, ffn_m, ffn_v, nullptr);

    // K5: ffn2 + residual(g_inter) + bn2 -> out (coalesced NCHW scatter)
    gemm_kernel<3><<<PP/64, 512, SMEM_Y_BYTES>>>(nullptr, ffn_w2,
        nullptr, nullptr, bn2_g, bn2_b, bn2_m, bn2_v, out);
}

// round 7
// speedup vs baseline: 1.6059x; 1.2361x over previous
#include <cuda_runtime.h>
#include <cuda_bf16.h>
#include <cstdint>
#include <math.h>

#define NB 8
#define CC 256
#define TT 120
#define VVC 25
#define PP (NB*TT*VVC)   // 24000 points
#define TV (TT*VVC)      // 3000
#define HH 8
#define HD 32
#define LLN 125
#define EPSV 1e-5f

// Scratch (device globals; no allocation anywhere)
__device__ __align__(16) float g_qkv[PP*768];    // (p, 768) cols = h*96 + s*32 + d
__device__ __align__(16) float g_ao[PP*256];     // mean-over-W attention out, (p, h*32+d)
__device__ __align__(16) float g_inter[PP*256];  // bn1 output, point-major
__device__ __align__(16) float g_h1[PP*256];     // ffn mid, point-major

// ---------------------------------------------------------------------------
// bf16 split helpers (x = hi + lo; hi,lo bf16; lo captures next 8 mantissa bits)
// ---------------------------------------------------------------------------
__device__ __forceinline__ void pksplit(float x, float y, uint32_t& hp, uint32_t& lp) {
    __nv_bfloat16 hx = __float2bfloat16_rn(x);
    __nv_bfloat16 hy = __float2bfloat16_rn(y);
    __nv_bfloat162 h2(hx, hy);
    hp = *reinterpret_cast<uint32_t*>(&h2);
    __nv_bfloat162 l2 = __floats2bfloat162_rn(x - __bfloat162float(hx),
                                              y - __bfloat162float(hy));
    lp = *reinterpret_cast<uint32_t*>(&l2);
}
__device__ __forceinline__ void scsplit(float v, __nv_bfloat16* ph, __nv_bfloat16* pl) {
    __nv_bfloat16 h = __float2bfloat16_rn(v);
    *ph = h;
    *pl = __float2bfloat16_rn(v - __bfloat162float(h));
}

#define MMA_BF16(c, a0, a1, a2, a3, b0, b1) \
    asm volatile("mma.sync.aligned.m16n8k16.row.col.f32.bf16.bf16.f32 " \
        "{%0,%1,%2,%3}, {%4,%5,%6,%7}, {%8,%9}, {%0,%1,%2,%3};" \
        : "+f"((c)[0]), "+f"((c)[1]), "+f"((c)[2]), "+f"((c)[3]) \
        : "r"(a0), "r"(a1), "r"(a2), "r"(a3), "r"(b0), "r"(b1))

// ---------------------------------------------------------------------------
// mma_gemm: 128-point x 128-col GEMM tile, K=256 (16 chunks of k16),
// mma.sync m16n8k16 bf16 with 2-term split (3 products; lolo dropped).
// 8 warps: warp (wm,wn) owns 64x32; per warp-tile 4x4 m16n8 frags.
// smem: 2 stages x {Ah, Al, Bh, Bl}, each 128 rows x 16 bf16, row stride
// 24 bf16 (48B -> conflict-free LDS: 12 banks/row, gcd(12,32)=4, 12/4 odd).
// MODE 0: qkv : A = x (NCHW gather), W=(in,out) ld=768 -> g_qkv (grid.y=6)
// MODE 1: proj: A = g_ao, W=w_out (in,out), +b_out +x bn1 -> g_inter
// MODE 2: ffn1: A = g_inter, W=ffn_w1 (out,in), mish bn -> g_h1
// MODE 3: ffn2: A = g_h1, W=ffn_w2 (out,in), +g_inter bn2 -> out (NCHW)
// ---------------------------------------------------------------------------
template<int MODE>
__global__ __launch_bounds__(256)
void mma_gemm(const float* __restrict__ Aext, const float* __restrict__ Wm,
              const float* __restrict__ bias, const float* __restrict__ res,
              const float* __restrict__ bg, const float* __restrict__ bb,
              const float* __restrict__ bm, const float* __restrict__ bv,
              float* __restrict__ outp)
{
    __shared__ __align__(16) __nv_bfloat16 smb[2][4][3072];  // 49152 B

    const int tid  = threadIdx.x;
    const int lane = tid & 31;
    const int wid  = tid >> 5;
    const int wm   = wid >> 2;          // 0..1 -> m offset wm*64
    const int wn   = wid & 3;           // 0..3 -> n offset wn*32
    const int p0   = blockIdx.x * 128;
    const int jb   = blockIdx.y * 128;
    const int ldw  = (MODE == 0) ? 768 : 256;

    const float* A;
    if constexpr (MODE == 0) A = Aext;
    else if constexpr (MODE == 1) A = g_ao;
    else if constexpr (MODE == 2) A = g_inter;
    else A = g_h1;

    float acc[4][4][4];
    #pragma unroll
    for (int mi = 0; mi < 4; ++mi)
        #pragma unroll
        for (int ni = 0; ni < 4; ++ni)
            #pragma unroll
            for (int q = 0; q < 4; ++q) acc[mi][ni][q] = 0.f;

    float rv[16];

    // ---- global load of chunk into registers ----
    auto ldg = [&](int chunk) {
        const int c0 = chunk * 16;
        if constexpr (MODE == 0) {
            int k = tid >> 4, plb = tid & 15;
            #pragma unroll
            for (int i = 0; i < 8; ++i) {
                int p = p0 + plb + i * 16; if (p >= PP) p = PP - 1;
                int n = p / TV, r = p - n * TV;
                rv[i] = Aext[(size_t)(n * CC + c0 + k) * TV + r];
            }
        } else {
            int pl = tid >> 1, half = tid & 1;
            int p = p0 + pl; if (p >= PP) p = PP - 1;
            const float* s = &A[(size_t)p * 256 + c0 + half * 8];
            *(float4*)&rv[0] = *(const float4*)s;
            *(float4*)&rv[4] = *(const float4*)(s + 4);
        }
        if constexpr (MODE <= 1) {
            int j = tid & 127, kh = tid >> 7;
            #pragma unroll
            for (int i = 0; i < 8; ++i)
                rv[8 + i] = Wm[(size_t)(c0 + kh * 8 + i) * ldw + jb + j];
        } else {
            int j = tid >> 1, half = tid & 1;
            const float* s = &Wm[(size_t)(jb + j) * 256 + c0 + half * 8];
            *(float4*)&rv[8]  = *(const float4*)s;
            *(float4*)&rv[12] = *(const float4*)(s + 4);
        }
    };

    // ---- split + store registers into stage st ----
    auto sts = [&](int st) {
        __nv_bfloat16* Ah = smb[st][0];
        __nv_bfloat16* Al = smb[st][1];
        __nv_bfloat16* Bh = smb[st][2];
        __nv_bfloat16* Bl = smb[st][3];
        if constexpr (MODE == 0) {
            int k = tid >> 4, plb = tid & 15;
            #pragma unroll
            for (int i = 0; i < 8; ++i) {
                int pl = plb + i * 16;
                scsplit(rv[i], &Ah[pl * 24 + k], &Al[pl * 24 + k]);
            }
        } else {
            int pl = tid >> 1, half = tid & 1;
            uint32_t h[4], l[4];
            #pragma unroll
            for (int q = 0; q < 4; ++q) pksplit(rv[2*q], rv[2*q+1], h[q], l[q]);
            *(uint4*)&Ah[pl * 24 + half * 8] = make_uint4(h[0], h[1], h[2], h[3]);
            *(uint4*)&Al[pl * 24 + half * 8] = make_uint4(l[0], l[1], l[2], l[3]);
        }
        if constexpr (MODE <= 1) {
            int j = tid & 127, kh = tid >> 7;
            #pragma unroll
            for (int i = 0; i < 8; ++i) {
                int k = kh * 8 + i;
                scsplit(rv[8 + i], &Bh[j * 24 + k], &Bl[j * 24 + k]);
            }
        } else {
            int j = tid >> 1, half = tid & 1;
            uint32_t h[4], l[4];
            #pragma unroll
            for (int q = 0; q < 4; ++q) pksplit(rv[8+2*q], rv[9+2*q], h[q], l[q]);
            *(uint4*)&Bh[j * 24 + half * 8] = make_uint4(h[0], h[1], h[2], h[3]);
            *(uint4*)&Bl[j * 24 + half * 8] = make_uint4(l[0], l[1], l[2], l[3]);
        }
    };

    // ---- mma over one stage ----
    auto compute = [&](int st) {
        const __nv_bfloat16* Ah = smb[st][0];
        const __nv_bfloat16* Al = smb[st][1];
        const __nv_bfloat16* Bh = smb[st][2];
        const __nv_bfloat16* Bl = smb[st][3];
        const int fr = lane >> 2;           // fragment row/col-group
        const int fc = (lane & 3) * 2;      // k (for A/B) base
        uint32_t bh[4][2], bl[4][2];
        #pragma unroll
        for (int ni = 0; ni < 4; ++ni) {
            const __nv_bfloat16* pb = &Bh[(wn*32 + ni*8 + fr) * 24 + fc];
            bh[ni][0] = *(const uint32_t*)pb;
            bh[ni][1] = *(const uint32_t*)(pb + 8);
            const __nv_bfloat16* pl_ = &Bl[(wn*32 + ni*8 + fr) * 24 + fc];
            bl[ni][0] = *(const uint32_t*)pl_;
            bl[ni][1] = *(const uint32_t*)(pl_ + 8);
        }
        #pragma unroll
        for (int mi = 0; mi < 4; ++mi) {
            const int ar = wm*64 + mi*16 + fr;
            const __nv_bfloat16* pa = &Ah[ar * 24 + fc];
            uint32_t ah0 = *(const uint32_t*)pa;
            uint32_t ah1 = *(const uint32_t*)(pa + 8*24);
            uint32_t ah2 = *(const uint32_t*)(pa + 8);
            uint32_t ah3 = *(const uint32_t*)(pa + 8*24 + 8);
            const __nv_bfloat16* qa = &Al[ar * 24 + fc];
            uint32_t al0 = *(const uint32_t*)qa;
            uint32_t al1 = *(const uint32_t*)(qa + 8*24);
            uint32_t al2 = *(const uint32_t*)(qa + 8);
            uint32_t al3 = *(const uint32_t*)(qa + 8*24 + 8);
            #pragma unroll
            for (int ni = 0; ni < 4; ++ni) {
                MMA_BF16(acc[mi][ni], ah0, ah1, ah2, ah3, bh[ni][0], bh[ni][1]);
                MMA_BF16(acc[mi][ni], ah0, ah1, ah2, ah3, bl[ni][0], bl[ni][1]);
                MMA_BF16(acc[mi][ni], al0, al1, al2, al3, bh[ni][0], bh[ni][1]);
            }
        }
    };

    // ---- pipelined main loop ----
    ldg(0); sts(0); __syncthreads();
    #pragma unroll 1
    for (int c = 0; c < 16; ++c) {
        if (c < 15) ldg(c + 1);
        compute(c & 1);
        __syncthreads();
        if (c < 15) { sts((c + 1) & 1); __syncthreads(); }
    }

    // ---- epilogues ----
    const int fr = lane >> 2;
    const int fc = (lane & 3) * 2;

    if constexpr (MODE == 0) {
        #pragma unroll
        for (int mi = 0; mi < 4; ++mi) {
            int pr = p0 + wm*64 + mi*16 + fr;
            #pragma unroll
            for (int ni = 0; ni < 4; ++ni) {
                int jc = jb + wn*32 + ni*8 + fc;
                if (pr < PP)
                    *(float2*)&g_qkv[(size_t)pr*768 + jc] =
                        make_float2(acc[mi][ni][0], acc[mi][ni][1]);
                if (pr + 8 < PP)
                    *(float2*)&g_qkv[(size_t)(pr+8)*768 + jc] =
                        make_float2(acc[mi][ni][2], acc[mi][ni][3]);
            }
        }
        return;
    }

    // BN constants per owned column pair
    float sc[4][2], be[4][2], bo[4][2];
    #pragma unroll
    for (int ni = 0; ni < 4; ++ni)
        #pragma unroll
        for (int q = 0; q < 2; ++q) {
            int j = jb + wn*32 + ni*8 + fc + q;
            float s = rsqrtf(bv[j] + EPSV) * bg[j];
            sc[ni][q] = s;
            be[ni][q] = bb[j] - bm[j] * s;
            bo[ni][q] = (MODE == 1) ? bias[j] : 0.f;
        }

    if constexpr (MODE == 2) {
        #pragma unroll
        for (int mi = 0; mi < 4; ++mi) {
            int pr = p0 + wm*64 + mi*16 + fr;
            #pragma unroll
            for (int ni = 0; ni < 4; ++ni) {
                int jc = jb + wn*32 + ni*8 + fc;
                float v[4];
                #pragma unroll
                for (int q = 0; q < 4; ++q) {
                    float a = acc[mi][ni][q];
                    float sp = (a > 20.f) ? a : log1pf(__expf(a));
                    v[q] = a * tanhf(sp) * sc[ni][q & 1] + be[ni][q & 1];
                }
                if (pr < PP)
                    *(float2*)&g_h1[(size_t)pr*256 + jc] = make_float2(v[0], v[1]);
                if (pr + 8 < PP)
                    *(float2*)&g_h1[(size_t)(pr+8)*256 + jc] = make_float2(v[2], v[3]);
            }
        }
        return;
    }

    float* stg = (float*)smb;   // [64][132] floats, reuses stage smem

    if constexpr (MODE == 1) {
        #pragma unroll 1
        for (int ph = 0; ph < 2; ++ph) {
            __syncthreads();
            // coalesced NCHW gather of x residual rows [p0+ph*64, +64)
            for (int idx = tid; idx < 64 * 128; idx += 256) {
                int pl = idx & 63, j = idx >> 6;
                int p = p0 + ph*64 + pl; if (p >= PP) p = PP - 1;
                int n = p / TV, r = p - n * TV;
                stg[pl*132 + j] = res[(size_t)(n * CC + jb + j) * TV + r];
            }
            __syncthreads();
            if (wm == ph) {
                #pragma unroll
                for (int mi = 0; mi < 4; ++mi) {
                    int lr = mi*16 + fr;
                    int pr = p0 + ph*64 + lr;
                    #pragma unroll
                    for (int ni = 0; ni < 4; ++ni) {
                        int jl = wn*32 + ni*8 + fc;
                        float2 x0 = *(float2*)&stg[lr*132 + jl];
                        float2 x1 = *(float2*)&stg[(lr+8)*132 + jl];
                        float v0 = (acc[mi][ni][0] + bo[ni][0] + x0.x)*sc[ni][0] + be[ni][0];
                        float v1 = (acc[mi][ni][1] + bo[ni][1] + x0.y)*sc[ni][1] + be[ni][1];
                        float v2 = (acc[mi][ni][2] + bo[ni][0] + x1.x)*sc[ni][0] + be[ni][0];
                        float v3 = (acc[mi][ni][3] + bo[ni][1] + x1.y)*sc[ni][1] + be[ni][1];
                        if (pr < PP)
                            *(float2*)&g_inter[(size_t)pr*256 + jb + jl] = make_float2(v0, v1);
                        if (pr + 8 < PP)
                            *(float2*)&g_inter[(size_t)(pr+8)*256 + jb + jl] = make_float2(v2, v3);
                    }
                }
            }
        }
        return;
    }

    // MODE 3: residual + bn2, staged transpose, coalesced NCHW scatter
    #pragma unroll 1
    for (int ph = 0; ph < 2; ++ph) {
        __syncthreads();
        if (wm == ph) {
            #pragma unroll
            for (int mi = 0; mi < 4; ++mi) {
                int lr = mi*16 + fr;
                int pr = p0 + ph*64 + lr;
                int p0c = (pr < PP) ? pr : PP - 1;
                int p1c = (pr + 8 < PP) ? pr + 8 : PP - 1;
                #pragma unroll
                for (int ni = 0; ni < 4; ++ni) {
                    int jl = wn*32 + ni*8 + fc;
                    float2 r0 = *(float2*)&g_inter[(size_t)p0c*256 + jb + jl];
                    float2 r1 = *(float2*)&g_inter[(size_t)p1c*256 + jb + jl];
                    stg[lr*132 + jl]       = (acc[mi][ni][0] + r0.x)*sc[ni][0] + be[ni][0];
                    stg[lr*132 + jl + 1]   = (acc[mi][ni][1] + r0.y)*sc[ni][1] + be[ni][1];
                    stg[(lr+8)*132 + jl]   = (acc[mi][ni][2] + r1.x)*sc[ni][0] + be[ni][0];
                    stg[(lr+8)*132 + jl+1] = (acc[mi][ni][3] + r1.y)*sc[ni][1] + be[ni][1];
                }
            }
        }
        __syncthreads();
        for (int idx = tid; idx < 64 * 128; idx += 256) {
            int pl = idx & 63, j = idx >> 6;
            int p = p0 + ph*64 + pl;
            if (p < PP) {
                int n = p / TV, r = p - n * TV;
                outp[(size_t)(n * CC + jb + j) * TV + r] = stg[pl*132 + j];
            }
        }
    }
}

// ---------------------------------------------------------------------------
// Attention (unchanged, known-good): one block per (n*T + t, head), 2 CTAs/SM.
// mean_w(softmax_rows @ V) = (mean_w softmax_rows) @ V -> SV GEMM 5x smaller.
// ---------------------------------------------------------------------------
#define AT_S    0
#define AT_K    16500
#define AT_Q    20724
#define AT_V    AT_K
#define AT_SUM  (AT_K + 4096)
#define AT_SB   AT_Q
#define ATTN_SMEM_FLOATS 24948

__global__ __launch_bounds__(256, 2)
void attn_kernel()
{
    extern __shared__ float smA[];
    float* S    = smA + AT_S;
    float* ks_t = smA + AT_K;
    float* qs_t = smA + AT_Q;
    float* vs   = smA + AT_V;
    float* sums = smA + AT_SUM;
    float* Sb   = smA + AT_SB;

    const int tid = threadIdx.x;
    const int bx = blockIdx.x, h = blockIdx.y;
    const int n = bx / TT, t = bx - n * TT;

    for (int lin = tid; lin < 4096; lin += 256) {
        int m = lin >> 5, d = lin & 31;
        float q = 0.f, k = 0.f;
        if (m < LLN) {
            int w = m / VVC;
            int vv = m - w * VVC;
            int ti = t + w - 2;
            if (ti >= 0 && ti < TT) {
                const float* bp = &g_qkv[((size_t)((n*TT + ti)*VVC + vv))*768 + h*96 + d];
                q = bp[0]; k = bp[32];
            }
        }
        qs_t[d*132 + m] = q;
        ks_t[d*132 + m] = k;
    }
    __syncthreads();

    {
        const int ty = tid >> 4, tx = tid & 15;
        float acc[8][8];
        #pragma unroll
        for (int i = 0; i < 8; ++i)
            #pragma unroll
            for (int j = 0; j < 8; ++j) acc[i][j] = 0.f;
        #pragma unroll 8
        for (int d = 0; d < 32; ++d) {
            float a[8], b[8];
            *(float4*)&a[0] = *(const float4*)&qs_t[d*132 + ty*8];
            *(float4*)&a[4] = *(const float4*)&qs_t[d*132 + ty*8 + 4];
            *(float4*)&b[0] = *(const float4*)&ks_t[d*132 + tx*8];
            *(float4*)&b[4] = *(const float4*)&ks_t[d*132 + tx*8 + 4];
            #pragma unroll
            for (int i = 0; i < 8; ++i)
                #pragma unroll
                for (int j = 0; j < 8; ++j)
                    acc[i][j] = fmaf(a[i], b[j], acc[i][j]);
        }
        #pragma unroll
        for (int i = 0; i < 8; ++i) {
            int l = ty*8 + i;
            if (l < LLN) {
                float tmp[8];
                #pragma unroll
                for (int j = 0; j < 8; ++j) tmp[j] = acc[i][j] * 0.0625f;
                if (tx == 15) { tmp[5] = -1e30f; tmp[6] = -1e30f; tmp[7] = -1e30f; }
                *(float4*)&S[l*132 + tx*8]     = *(float4*)&tmp[0];
                *(float4*)&S[l*132 + tx*8 + 4] = *(float4*)&tmp[4];
            }
        }
    }
    __syncthreads();

    for (int lin = tid; lin < 4096; lin += 256) {
        int m = lin >> 5, d = lin & 31;
        float v = 0.f;
        if (m < LLN) {
            int w = m / VVC;
            int vv = m - w * VVC;
            int ti = t + w - 2;
            if (ti >= 0 && ti < TT)
                v = g_qkv[((size_t)((n*TT + ti)*VVC + vv))*768 + h*96 + 64 + d];
        }
        vs[m*32 + d] = v;
    }
    if (tid < LLN) {
        const int l = tid;
        float4* row = (float4*)&S[l*132];
        float mx = -1e30f;
        #pragma unroll
        for (int i = 0; i < 32; ++i) {
            float4 f = row[i];
            mx = fmaxf(mx, fmaxf(fmaxf(f.x, f.y), fmaxf(f.z, f.w)));
        }
        float s = 0.f;
        #pragma unroll
        for (int i = 0; i < 32; ++i) {
            float4 f = row[i];
            f.x = __expf(f.x - mx); f.y = __expf(f.y - mx);
            f.z = __expf(f.z - mx); f.w = __expf(f.w - mx);
            s += f.x + f.y + f.z + f.w;
            row[i] = f;
        }
        sums[l] = 0.2f / s;
    }
    __syncthreads();

    for (int task = tid; task < 25*32; task += 256) {
        int v = task >> 5, i4 = task & 31;
        float4 r = make_float4(0.f, 0.f, 0.f, 0.f);
        #pragma unroll
        for (int w = 0; w < 5; ++w) {
            int l = w*VVC + v;
            float rs = sums[l];
            float4 f = *(const float4*)&S[l*132 + i4*4];
            r.x = fmaf(f.x, rs, r.x); r.y = fmaf(f.y, rs, r.y);
            r.z = fmaf(f.z, rs, r.z); r.w = fmaf(f.w, rs, r.w);
        }
        *(float4*)&Sb[v*132 + i4*4] = r;
    }
    __syncthreads();

    if (tid < 200) {
        const int v = tid >> 3, g = tid & 7;
        float4 acc = make_float4(0.f, 0.f, 0.f, 0.f);
        #pragma unroll 8
        for (int m = 0; m < 128; ++m) {
            float a = Sb[v*132 + m];
            float4 b = *(const float4*)&vs[m*32 + g*4];
            acc.x = fmaf(a, b.x, acc.x); acc.y = fmaf(a, b.y, acc.y);
            acc.z = fmaf(a, b.z, acc.z); acc.w = fmaf(a, b.w, acc.w);
        }
        *(float4*)&g_ao[((size_t)((n*TT + t)*VVC + v))*256 + h*HD + g*4] = acc;
    }
}

// ---------------------------------------------------------------------------
extern "C" void kernel_launch(void* const* d_in, const int* in_sizes, int n_in,
                              void* d_out, int out_size)
{
    const float* x      = (const float*)d_in[0];
    const float* w_qkv  = (const float*)d_in[1];
    const float* w_out  = (const float*)d_in[2];
    const float* b_out  = (const float*)d_in[3];
    const float* bn1_g  = (const float*)d_in[4];
    const float* bn1_b  = (const float*)d_in[5];
    const float* ffn_w1 = (const float*)d_in[6];
    const float* ffn_w2 = (const float*)d_in[7];
    const float* ffn_g  = (const float*)d_in[8];
    const float* ffn_b  = (const float*)d_in[9];
    const float* bn2_g  = (const float*)d_in[10];
    const float* bn2_b  = (const float*)d_in[11];
    const float* bn1_m  = (const float*)d_in[12];
    const float* bn1_v  = (const float*)d_in[13];
    const float* ffn_m  = (const float*)d_in[14];
    const float* ffn_v  = (const float*)d_in[15];
    const float* bn2_m  = (const float*)d_in[16];
    const float* bn2_v  = (const float*)d_in[17];
    float* out = (float*)d_out;

    static int attr_done = 0;
    if (!attr_done) {
        cudaFuncSetAttribute(attn_kernel,
            cudaFuncAttributeMaxDynamicSharedMemorySize, ATTN_SMEM_FLOATS * 4);
        attr_done = 1;
    }

    const int MT = (PP + 127) / 128;   // 188 M-tiles

    // K1: QKV projection (N=768 via 6 column tiles)
    mma_gemm<0><<<dim3(MT, 6), 256>>>(x, w_qkv,
        nullptr, nullptr, nullptr, nullptr, nullptr, nullptr, nullptr);

    // K2: attention + window mean
    attn_kernel<<<dim3(NB*TT, HH), 256, ATTN_SMEM_FLOATS * 4>>>();

    // K3: out projection + b_out + x residual + bn1 -> g_inter
    mma_gemm<1><<<dim3(MT, 2), 256>>>(nullptr, w_out,
        b_out, x, bn1_g, bn1_b, bn1_m, bn1_v, nullptr);

    // K4: ffn1 + mish + bn(ffn) -> g_h1
    mma_gemm<2><<<dim3(MT, 2), 256>>>(nullptr, ffn_w1,
        nullptr, nullptr, ffn_g, ffn_b, ffn_m, ffn_v, nullptr);

    // K5: ffn2 + residual(g_inter) + bn2 -> out (NCHW scatter)
    mma_gemm<3><<<dim3(MT, 2), 256>>>(nullptr, ffn_w2,
        nullptr, nullptr, bn2_g, bn2_b, bn2_m, bn2_v, out);
}

// round 8
// speedup vs baseline: 2.0044x; 1.2481x over previous
#include <cuda_runtime.h>
#include <cuda_bf16.h>
#include <cstdint>
#include <math.h>

#define NB 8
#define CC 256
#define TT 120
#define VVC 25
#define PP (NB*TT*VVC)   // 24000 points
#define TV (TT*VVC)      // 3000
#define HH 8
#define HD 32
#define LLN 125
#define EPSV 1e-5f

#define WQ_OFF 0
#define WO_OFF 196608
#define W1_OFF 262144
#define W2_OFF 327680
#define WTOT   393216

// Scratch (device globals; no allocation anywhere)
__device__ __align__(16) float g_qkv[PP*768];            // fp32, attention input
__device__ __align__(16) __nv_bfloat16 xs_h[PP*256];     // x transposed+split
__device__ __align__(16) __nv_bfloat16 xs_l[PP*256];
__device__ __align__(16) __nv_bfloat16 g_aoh[PP*256];    // attention out planes
__device__ __align__(16) __nv_bfloat16 g_aol[PP*256];
__device__ __align__(16) __nv_bfloat16 g_inth[PP*256];   // bn1 out planes
__device__ __align__(16) __nv_bfloat16 g_intl[PP*256];
__device__ __align__(16) __nv_bfloat16 g_h1h[PP*256];    // ffn mid planes
__device__ __align__(16) __nv_bfloat16 g_h1l[PP*256];
__device__ __align__(16) __nv_bfloat16 wsp_h[WTOT];      // weights [out][in]
__device__ __align__(16) __nv_bfloat16 wsp_l[WTOT];

// ---------------------------------------------------------------------------
__device__ __forceinline__ void cp16(void* dst, const void* src) {
    unsigned int d = (unsigned int)__cvta_generic_to_shared(dst);
    asm volatile("cp.async.cg.shared.global [%0], [%1], 16;\n" :: "r"(d), "l"(src));
}
#define CP_COMMIT() asm volatile("cp.async.commit_group;\n" ::: "memory")
#define CP_WAIT1()  asm volatile("cp.async.wait_group 1;\n" ::: "memory")
#define CP_WAIT0()  asm volatile("cp.async.wait_group 0;\n" ::: "memory")

#define MMA_BF16(c, a0, a1, a2, a3, b0, b1) \
    asm volatile("mma.sync.aligned.m16n8k16.row.col.f32.bf16.bf16.f32 " \
        "{%0,%1,%2,%3}, {%4,%5,%6,%7}, {%8,%9}, {%0,%1,%2,%3};" \
        : "+f"((c)[0]), "+f"((c)[1]), "+f"((c)[2]), "+f"((c)[3]) \
        : "r"(a0), "r"(a1), "r"(a2), "r"(a3), "r"(b0), "r"(b1))

__device__ __forceinline__ void store_split2(__nv_bfloat16* dh, __nv_bfloat16* dl,
                                             size_t o, float v0, float v1) {
    __nv_bfloat16 h0 = __float2bfloat16_rn(v0);
    __nv_bfloat16 h1 = __float2bfloat16_rn(v1);
    __nv_bfloat162 hp; hp.x = h0; hp.y = h1;
    __nv_bfloat162 lp;
    lp.x = __float2bfloat16_rn(v0 - __bfloat162float(h0));
    lp.y = __float2bfloat16_rn(v1 - __bfloat162float(h1));
    *(__nv_bfloat162*)&dh[o] = hp;
    *(__nv_bfloat162*)&dl[o] = lp;
}
__device__ __forceinline__ float2 load_split2(const __nv_bfloat16* dh,
                                              const __nv_bfloat16* dl, size_t o) {
    __nv_bfloat162 h = *(const __nv_bfloat162*)&dh[o];
    __nv_bfloat162 l = *(const __nv_bfloat162*)&dl[o];
    return make_float2(__bfloat162float(h.x) + __bfloat162float(l.x),
                       __bfloat162float(h.y) + __bfloat162float(l.y));
}

// ---------------------------------------------------------------------------
// prep_w: split 4 weight matrices into bf16 hi/lo planes, [out][in] layout.
// ---------------------------------------------------------------------------
__global__ __launch_bounds__(256) void prep_w(const float* __restrict__ wq,
                                              const float* __restrict__ wo,
                                              const float* __restrict__ w1,
                                              const float* __restrict__ w2)
{
    int idx = blockIdx.x * 256 + threadIdx.x;
    if (idx >= WTOT) return;
    float v;
    if (idx < WO_OFF)      { int j = idx >> 8, k = idx & 255; v = wq[k*768 + j]; }
    else if (idx < W1_OFF) { int l = idx - WO_OFF; int j = l >> 8, k = l & 255; v = wo[k*256 + j]; }
    else if (idx < W2_OFF) { v = w1[idx - W1_OFF]; }
    else                   { v = w2[idx - W2_OFF]; }
    __nv_bfloat16 h = __float2bfloat16_rn(v);
    wsp_h[idx] = h;
    wsp_l[idx] = __float2bfloat16_rn(v - __bfloat162float(h));
}

// ---------------------------------------------------------------------------
// prep_x: transpose x (NCHW -> point-major) and split into bf16 planes.
// Block handles 64 points x 256 channels via smem staging.
// ---------------------------------------------------------------------------
#define PXSMEM (2*64*264*2)   // 67584 bytes
__global__ __launch_bounds__(256) void prep_x(const float* __restrict__ x)
{
    extern __shared__ __nv_bfloat16 sx[];
    __nv_bfloat16* sh = sx;
    __nv_bfloat16* sl = sx + 64*264;
    const int tid = threadIdx.x;
    const int p0 = blockIdx.x * 64;
    #pragma unroll 4
    for (int it = 0; it < 64; ++it) {
        int lin = it * 256 + tid;
        int pl = lin & 63, cl = lin >> 6;
        int p = p0 + pl;
        int n = p / TV, r = p - n * TV;
        float v = x[(size_t)(n*CC + cl)*TV + r];
        __nv_bfloat16 h = __float2bfloat16_rn(v);
        sh[pl*264 + cl] = h;
        sl[pl*264 + cl] = __float2bfloat16_rn(v - __bfloat162float(h));
    }
    __syncthreads();
    #pragma unroll
    for (int s = tid; s < 2048; s += 256) {
        int pl = s >> 5, seg = s & 31;
        *(uint4*)&xs_h[(size_t)(p0+pl)*256 + seg*8] = *(uint4*)&sh[pl*264 + seg*8];
        *(uint4*)&xs_l[(size_t)(p0+pl)*256 + seg*8] = *(uint4*)&sl[pl*264 + seg*8];
    }
}

// ---------------------------------------------------------------------------
// mma_gemm: 128 x 128 tile, K=256 in 8 chunks of k32. A and B come from
// pre-split bf16 planes via cp.async (no conversion in the mainloop).
// 2-term split product (3 MMAs): D = AhBh + AhBl + AlBh.
// smem/stage: Ah,Al,Bh,Bl each [128][40] bf16 (stride 40 -> conflict-free).
// MODE 0: A=xs, B=wq -> g_qkv fp32 (grid.y=6)
// MODE 1: A=g_ao, B=wo, +b_out +x(split) bn1 -> g_int planes
// MODE 2: A=g_int, B=w1, mish bn -> g_h1 planes
// MODE 3: A=g_h1, B=w2, +g_int(split) bn2 -> out NCHW
// ---------------------------------------------------------------------------
#define GSTG 20480                     // bf16 per stage
#define GSMEM (2*GSTG*2)               // 81920 bytes

template<int MODE>
__global__ __launch_bounds__(256)
void mma_gemm(const float* __restrict__ bias,
              const float* __restrict__ bg, const float* __restrict__ bb,
              const float* __restrict__ bm, const float* __restrict__ bv,
              float* __restrict__ outp)
{
    extern __shared__ __nv_bfloat16 smb[];

    const int tid  = threadIdx.x;
    const int lane = tid & 31;
    const int wid  = tid >> 5;
    const int wm   = wid >> 2;
    const int wn   = wid & 3;
    const int p0   = blockIdx.x * 128;
    const int jb   = blockIdx.y * 128;

    const __nv_bfloat16* Asrc_h;
    const __nv_bfloat16* Asrc_l;
    int woff;
    if constexpr (MODE == 0) { Asrc_h = xs_h;   Asrc_l = xs_l;   woff = WQ_OFF; }
    else if constexpr (MODE == 1) { Asrc_h = g_aoh;  Asrc_l = g_aol;  woff = WO_OFF; }
    else if constexpr (MODE == 2) { Asrc_h = g_inth; Asrc_l = g_intl; woff = W1_OFF; }
    else { Asrc_h = g_h1h; Asrc_l = g_h1l; woff = W2_OFF; }

    float acc[4][4][4];
    #pragma unroll
    for (int mi = 0; mi < 4; ++mi)
        #pragma unroll
        for (int ni = 0; ni < 4; ++ni)
            #pragma unroll
            for (int q = 0; q < 4; ++q) acc[mi][ni][q] = 0.f;

    auto fill = [&](int c, int st) {
        const int c0 = c * 32;
        __nv_bfloat16* Sg = smb + st * GSTG;
        #pragma unroll
        for (int i = 0; i < 8; ++i) {
            int s = i * 256 + tid;        // 0..2047
            int plane = s >> 9;           // 0:Ah 1:Al 2:Bh 3:Bl
            int e = s & 511;
            int row = e >> 2, sg = e & 3;
            const __nv_bfloat16* src;
            if (plane == 0) {
                int p = p0 + row; if (p >= PP) p = PP - 1;
                src = &Asrc_h[(size_t)p*256 + c0 + sg*8];
            } else if (plane == 1) {
                int p = p0 + row; if (p >= PP) p = PP - 1;
                src = &Asrc_l[(size_t)p*256 + c0 + sg*8];
            } else if (plane == 2) {
                src = &wsp_h[(size_t)woff + (size_t)(jb + row)*256 + c0 + sg*8];
            } else {
                src = &wsp_l[(size_t)woff + (size_t)(jb + row)*256 + c0 + sg*8];
            }
            cp16(&Sg[plane*5120 + row*40 + sg*8], src);
        }
    };

    auto compute = [&](int st) {
        const __nv_bfloat16* Ah = smb + st * GSTG;
        const __nv_bfloat16* Al = Ah + 5120;
        const __nv_bfloat16* Bh = Ah + 10240;
        const __nv_bfloat16* Bl = Ah + 15360;
        const int fr = lane >> 2;
        const int fc = (lane & 3) * 2;
        #pragma unroll
        for (int kh = 0; kh < 2; ++kh) {
            const int ko = kh * 16;
            uint32_t bh[4][2], bl[4][2];
            #pragma unroll
            for (int ni = 0; ni < 4; ++ni) {
                const __nv_bfloat16* pb = &Bh[(wn*32 + ni*8 + fr)*40 + ko + fc];
                bh[ni][0] = *(const uint32_t*)pb;
                bh[ni][1] = *(const uint32_t*)(pb + 8);
                const __nv_bfloat16* ql = &Bl[(wn*32 + ni*8 + fr)*40 + ko + fc];
                bl[ni][0] = *(const uint32_t*)ql;
                bl[ni][1] = *(const uint32_t*)(ql + 8);
            }
            #pragma unroll
            for (int mi = 0; mi < 4; ++mi) {
                const int ar = wm*64 + mi*16 + fr;
                const __nv_bfloat16* pa = &Ah[ar*40 + ko + fc];
                uint32_t ah0 = *(const uint32_t*)pa;
                uint32_t ah1 = *(const uint32_t*)(pa + 8*40);
                uint32_t ah2 = *(const uint32_t*)(pa + 8);
                uint32_t ah3 = *(const uint32_t*)(pa + 8*40 + 8);
                const __nv_bfloat16* qa = &Al[ar*40 + ko + fc];
                uint32_t al0 = *(const uint32_t*)qa;
                uint32_t al1 = *(const uint32_t*)(qa + 8*40);
                uint32_t al2 = *(const uint32_t*)(qa + 8);
                uint32_t al3 = *(const uint32_t*)(qa + 8*40 + 8);
                #pragma unroll
                for (int ni = 0; ni < 4; ++ni) {
                    MMA_BF16(acc[mi][ni], ah0, ah1, ah2, ah3, bh[ni][0], bh[ni][1]);
                    MMA_BF16(acc[mi][ni], ah0, ah1, ah2, ah3, bl[ni][0], bl[ni][1]);
                    MMA_BF16(acc[mi][ni], al0, al1, al2, al3, bh[ni][0], bh[ni][1]);
                }
            }
        }
    };

    fill(0, 0); CP_COMMIT();
    int st = 0;
    #pragma unroll 1
    for (int c = 0; c < 8; ++c) {
        if (c < 7) { fill(c + 1, st ^ 1); CP_COMMIT(); CP_WAIT1(); }
        else       { CP_WAIT0(); }
        __syncthreads();
        compute(st);
        __syncthreads();
        st ^= 1;
    }

    // ---- epilogues ----
    const int fr = lane >> 2;
    const int fc = (lane & 3) * 2;

    if constexpr (MODE == 0) {
        #pragma unroll
        for (int mi = 0; mi < 4; ++mi) {
            int pr = p0 + wm*64 + mi*16 + fr;
            #pragma unroll
            for (int ni = 0; ni < 4; ++ni) {
                int jc = jb + wn*32 + ni*8 + fc;
                if (pr < PP)
                    *(float2*)&g_qkv[(size_t)pr*768 + jc] =
                        make_float2(acc[mi][ni][0], acc[mi][ni][1]);
                if (pr + 8 < PP)
                    *(float2*)&g_qkv[(size_t)(pr+8)*768 + jc] =
                        make_float2(acc[mi][ni][2], acc[mi][ni][3]);
            }
        }
        return;
    }

    float sc[4][2], be[4][2], bo[4][2];
    #pragma unroll
    for (int ni = 0; ni < 4; ++ni)
        #pragma unroll
        for (int q = 0; q < 2; ++q) {
            int j = jb + wn*32 + ni*8 + fc + q;
            float s = rsqrtf(bv[j] + EPSV) * bg[j];
            sc[ni][q] = s;
            be[ni][q] = bb[j] - bm[j] * s;
            bo[ni][q] = (MODE == 1) ? bias[j] : 0.f;
        }

    if constexpr (MODE == 1) {
        #pragma unroll
        for (int mi = 0; mi < 4; ++mi) {
            int pr = p0 + wm*64 + mi*16 + fr;
            #pragma unroll
            for (int ni = 0; ni < 4; ++ni) {
                int jc = jb + wn*32 + ni*8 + fc;
                if (pr < PP) {
                    size_t o = (size_t)pr*256 + jc;
                    float2 xr = load_split2(xs_h, xs_l, o);
                    float v0 = (acc[mi][ni][0] + bo[ni][0] + xr.x)*sc[ni][0] + be[ni][0];
                    float v1 = (acc[mi][ni][1] + bo[ni][1] + xr.y)*sc[ni][1] + be[ni][1];
                    store_split2(g_inth, g_intl, o, v0, v1);
                }
                if (pr + 8 < PP) {
                    size_t o = (size_t)(pr+8)*256 + jc;
                    float2 xr = load_split2(xs_h, xs_l, o);
                    float v2 = (acc[mi][ni][2] + bo[ni][0] + xr.x)*sc[ni][0] + be[ni][0];
                    float v3 = (acc[mi][ni][3] + bo[ni][1] + xr.y)*sc[ni][1] + be[ni][1];
                    store_split2(g_inth, g_intl, o, v2, v3);
                }
            }
        }
        return;
    }

    if constexpr (MODE == 2) {
        #pragma unroll
        for (int mi = 0; mi < 4; ++mi) {
            int pr = p0 + wm*64 + mi*16 + fr;
            #pragma unroll
            for (int ni = 0; ni < 4; ++ni) {
                int jc = jb + wn*32 + ni*8 + fc;
                float v[4];
                #pragma unroll
                for (int q = 0; q < 4; ++q) {
                    float a = acc[mi][ni][q];
                    float sp = (a > 20.f) ? a : log1pf(__expf(a));
                    v[q] = a * tanhf(sp) * sc[ni][q & 1] + be[ni][q & 1];
                }
                if (pr < PP)
                    store_split2(g_h1h, g_h1l, (size_t)pr*256 + jc, v[0], v[1]);
                if (pr + 8 < PP)
                    store_split2(g_h1h, g_h1l, (size_t)(pr+8)*256 + jc, v[2], v[3]);
            }
        }
        return;
    }

    // MODE 3: residual(split) + bn2, staged transpose, coalesced NCHW scatter
    float* stg = (float*)smb;   // [64][132] floats
    #pragma unroll 1
    for (int ph = 0; ph < 2; ++ph) {
        __syncthreads();
        if (wm == ph) {
            #pragma unroll
            for (int mi = 0; mi < 4; ++mi) {
                int lr = mi*16 + fr;
                int pr = p0 + ph*64 + lr;
                int p0c = (pr < PP) ? pr : PP - 1;
                int p1c = (pr + 8 < PP) ? pr + 8 : PP - 1;
                #pragma unroll
                for (int ni = 0; ni < 4; ++ni) {
                    int jl = wn*32 + ni*8 + fc;
                    float2 r0 = load_split2(g_inth, g_intl, (size_t)p0c*256 + jb + jl);
                    float2 r1 = load_split2(g_inth, g_intl, (size_t)p1c*256 + jb + jl);
                    stg[lr*132 + jl]       = (acc[mi][ni][0] + r0.x)*sc[ni][0] + be[ni][0];
                    stg[lr*132 + jl + 1]   = (acc[mi][ni][1] + r0.y)*sc[ni][1] + be[ni][1];
                    stg[(lr+8)*132 + jl]   = (acc[mi][ni][2] + r1.x)*sc[ni][0] + be[ni][0];
                    stg[(lr+8)*132 + jl+1] = (acc[mi][ni][3] + r1.y)*sc[ni][1] + be[ni][1];
                }
            }
        }
        __syncthreads();
        for (int idx = tid; idx < 64 * 128; idx += 256) {
            int pl = idx & 63, j = idx >> 6;
            int p = p0 + ph*64 + pl;
            if (p < PP) {
                int n = p / TV, r = p - n * TV;
                outp[(size_t)(n * CC + jb + j) * TV + r] = stg[pl*132 + j];
            }
        }
    }
}

// ---------------------------------------------------------------------------
// Attention: one block per (n*T + t, head), 2 CTAs/SM. Vectorized gathers,
// no-max single-pass softmax (scores are tiny; padded cols -1e30 -> exp = 0),
// mean_w folded before SV. Writes g_ao as split planes.
// ---------------------------------------------------------------------------
#define AT_S    0
#define AT_K    16500
#define AT_Q    20724
#define AT_V    AT_K
#define AT_SUM  (AT_K + 4096)
#define AT_SB   AT_Q
#define ATTN_SMEM_FLOATS 24948

__global__ __launch_bounds__(256, 2)
void attn_kernel()
{
    extern __shared__ float smA[];
    float* S    = smA + AT_S;
    float* ks_t = smA + AT_K;
    float* qs_t = smA + AT_Q;
    float* vs   = smA + AT_V;
    float* sums = smA + AT_SUM;
    float* Sb   = smA + AT_SB;

    const int tid = threadIdx.x;
    const int bx = blockIdx.x, h = blockIdx.y;
    const int n = bx / TT, t = bx - n * TT;

    // ---- phase 1: vectorized Q/K gather (float4; 8 rounds) ----
    for (int lin = tid; lin < 2000; lin += 256) {
        int m = lin >> 4;                // 0..124
        int c = lin & 15;                // 0..15 float4 slots (q:0-7, k:8-15)
        int w = m / VVC, vv = m - w * VVC;
        int ti = t + w - 2;
        float4 f = make_float4(0.f, 0.f, 0.f, 0.f);
        if (ti >= 0 && ti < TT)
            f = *(const float4*)&g_qkv[((size_t)((n*TT + ti)*VVC + vv))*768 + h*96 + c*4];
        float* dstb = (c < 8) ? qs_t : ks_t;
        int d = (c & 7) * 4;
        dstb[(d+0)*132 + m] = f.x;
        dstb[(d+1)*132 + m] = f.y;
        dstb[(d+2)*132 + m] = f.z;
        dstb[(d+3)*132 + m] = f.w;
    }
    if (tid < 96) {                      // zero rows 125..127
        int m = 125 + (tid >> 5), d = tid & 31;
        qs_t[d*132 + m] = 0.f;
        ks_t[d*132 + m] = 0.f;
    }
    __syncthreads();

    // ---- phase 2: S = Q K^T / 16 ----
    {
        const int ty = tid >> 4, tx = tid & 15;
        float acc[8][8];
        #pragma unroll
        for (int i = 0; i < 8; ++i)
            #pragma unroll
            for (int j = 0; j < 8; ++j) acc[i][j] = 0.f;
        #pragma unroll 8
        for (int d = 0; d < 32; ++d) {
            float a[8], b[8];
            *(float4*)&a[0] = *(const float4*)&qs_t[d*132 + ty*8];
            *(float4*)&a[4] = *(const float4*)&qs_t[d*132 + ty*8 + 4];
            *(float4*)&b[0] = *(const float4*)&ks_t[d*132 + tx*8];
            *(float4*)&b[4] = *(const float4*)&ks_t[d*132 + tx*8 + 4];
            #pragma unroll
            for (int i = 0; i < 8; ++i)
                #pragma unroll
                for (int j = 0; j < 8; ++j)
                    acc[i][j] = fmaf(a[i], b[j], acc[i][j]);
        }
        #pragma unroll
        for (int i = 0; i < 8; ++i) {
            int l = ty*8 + i;
            if (l < LLN) {
                float tmp[8];
                #pragma unroll
                for (int j = 0; j < 8; ++j) tmp[j] = acc[i][j] * 0.0625f;
                if (tx == 15) { tmp[5] = -1e30f; tmp[6] = -1e30f; tmp[7] = -1e30f; }
                *(float4*)&S[l*132 + tx*8]     = *(float4*)&tmp[0];
                *(float4*)&S[l*132 + tx*8 + 4] = *(float4*)&tmp[4];
            }
        }
    }
    __syncthreads();

    // ---- phase 3: V gather (over dead K region) + single-pass softmax ----
    for (int lin = tid; lin < 1000; lin += 256) {
        int m = lin >> 3, c = lin & 7;
        int w = m / VVC, vv = m - w * VVC;
        int ti = t + w - 2;
        float4 f = make_float4(0.f, 0.f, 0.f, 0.f);
        if (ti >= 0 && ti < TT)
            f = *(const float4*)&g_qkv[((size_t)((n*TT + ti)*VVC + vv))*768 + h*96 + 64 + c*4];
        *(float4*)&vs[m*32 + c*4] = f;
    }
    if (tid < 96) {
        int m = 125 + (tid >> 5), d = tid & 31;
        vs[m*32 + d] = 0.f;
    }
    if (tid < LLN) {
        const int l = tid;
        float4* row = (float4*)&S[l*132];
        float s = 0.f;
        #pragma unroll
        for (int i = 0; i < 32; ++i) {
            float4 f = row[i];
            f.x = __expf(f.x); f.y = __expf(f.y);
            f.z = __expf(f.z); f.w = __expf(f.w);
            s += f.x + f.y + f.z + f.w;
            row[i] = f;
        }
        sums[l] = 0.2f / s;              // fold 1/5 window mean
    }
    __syncthreads();

    // ---- phase 4: S-bar[v] = sum_w S[(w,v)] * (0.2/sum_w) ----
    for (int task = tid; task < 25*32; task += 256) {
        int v = task >> 5, i4 = task & 31;
        float4 r = make_float4(0.f, 0.f, 0.f, 0.f);
        #pragma unroll
        for (int w = 0; w < 5; ++w) {
            int l = w*VVC + v;
            float rs = sums[l];
            float4 f = *(const float4*)&S[l*132 + i4*4];
            r.x = fmaf(f.x, rs, r.x); r.y = fmaf(f.y, rs, r.y);
            r.z = fmaf(f.z, rs, r.z); r.w = fmaf(f.w, rs, r.w);
        }
        *(float4*)&Sb[v*132 + i4*4] = r;
    }
    __syncthreads();

    // ---- phase 5: O = S-bar @ V (25 x 32), split-write g_ao planes ----
    if (tid < 200) {
        const int v = tid >> 3, g = tid & 7;
        float4 acc = make_float4(0.f, 0.f, 0.f, 0.f);
        #pragma unroll 8
        for (int m = 0; m < 128; ++m) {
            float a = Sb[v*132 + m];
            float4 b = *(const float4*)&vs[m*32 + g*4];
            acc.x = fmaf(a, b.x, acc.x); acc.y = fmaf(a, b.y, acc.y);
            acc.z = fmaf(a, b.z, acc.z); acc.w = fmaf(a, b.w, acc.w);
        }
        size_t base = ((size_t)((n*TT + t)*VVC + v))*256 + h*HD + g*4;
        store_split2(g_aoh, g_aol, base,     acc.x, acc.y);
        store_split2(g_aoh, g_aol, base + 2, acc.z, acc.w);
    }
}

// ---------------------------------------------------------------------------
extern "C" void kernel_launch(void* const* d_in, const int* in_sizes, int n_in,
                              void* d_out, int out_size)
{
    const float* x      = (const float*)d_in[0];
    const float* w_qkv  = (const float*)d_in[1];
    const float* w_out  = (const float*)d_in[2];
    const float* b_out  = (const float*)d_in[3];
    const float* bn1_g  = (const float*)d_in[4];
    const float* bn1_b  = (const float*)d_in[5];
    const float* ffn_w1 = (const float*)d_in[6];
    const float* ffn_w2 = (const float*)d_in[7];
    const float* ffn_g  = (const float*)d_in[8];
    const float* ffn_b  = (const float*)d_in[9];
    const float* bn2_g  = (const float*)d_in[10];
    const float* bn2_b  = (const float*)d_in[11];
    const float* bn1_m  = (const float*)d_in[12];
    const float* bn1_v  = (const float*)d_in[13];
    const float* ffn_m  = (const float*)d_in[14];
    const float* ffn_v  = (const float*)d_in[15];
    const float* bn2_m  = (const float*)d_in[16];
    const float* bn2_v  = (const float*)d_in[17];
    float* out = (float*)d_out;

    static int attr_done = 0;
    if (!attr_done) {
        cudaFuncSetAttribute(attn_kernel,
            cudaFuncAttributeMaxDynamicSharedMemorySize, ATTN_SMEM_FLOATS * 4);
        cudaFuncSetAttribute(prep_x,
            cudaFuncAttributeMaxDynamicSharedMemorySize, PXSMEM);
        cudaFuncSetAttribute(mma_gemm<0>,
            cudaFuncAttributeMaxDynamicSharedMemorySize, GSMEM);
        cudaFuncSetAttribute(mma_gemm<1>,
            cudaFuncAttributeMaxDynamicSharedMemorySize, GSMEM);
        cudaFuncSetAttribute(mma_gemm<2>,
            cudaFuncAttributeMaxDynamicSharedMemorySize, GSMEM);
        cudaFuncSetAttribute(mma_gemm<3>,
            cudaFuncAttributeMaxDynamicSharedMemorySize, GSMEM);
        attr_done = 1;
    }

    const int MT = (PP + 127) / 128;   // 188 M-tiles

    // prep: split weights + transpose/split x
    prep_w<<<(WTOT + 255)/256, 256>>>(w_qkv, w_out, ffn_w1, ffn_w2);
    prep_x<<<PP/64, 256, PXSMEM>>>(x);

    // K1: QKV projection (N=768 via 6 column tiles)
    mma_gemm<0><<<dim3(MT, 6), 256, GSMEM>>>(
        nullptr, nullptr, nullptr, nullptr, nullptr, nullptr);

    // K2: attention + window mean
    attn_kernel<<<dim3(NB*TT, HH), 256, ATTN_SMEM_FLOATS * 4>>>();

    // K3: out projection + b_out + x residual + bn1 -> g_int planes
    mma_gemm<1><<<dim3(MT, 2), 256, GSMEM>>>(
        b_out, bn1_g, bn1_b, bn1_m, bn1_v, nullptr);

    // K4: ffn1 + mish + bn(ffn) -> g_h1 planes
    mma_gemm<2><<<dim3(MT, 2), 256, GSMEM>>>(
        nullptr, ffn_g, ffn_b, ffn_m, ffn_v, nullptr);

    // K5: ffn2 + residual + bn2 -> out (NCHW scatter)
    mma_gemm<3><<<dim3(MT, 2), 256, GSMEM>>>(
        nullptr, bn2_g, bn2_b, bn2_m, bn2_v, out);
}

// round 9
// speedup vs baseline: 2.3496x; 1.1723x over previous
#include <cuda_runtime.h>
#include <cuda_bf16.h>
#include <cstdint>
#include <math.h>

#define NB 8
#define CC 256
#define TT 120
#define VVC 25
#define PP (NB*TT*VVC)   // 24000 points
#define TV (TT*VVC)      // 3000
#define HH 8
#define HD 32
#define LLN 125
#define EPSV 1e-5f

#define WQ_OFF 0
#define WO_OFF 196608
#define W1_OFF 262144
#define W2_OFF 327680
#define WTOT   393216

// Scratch (device globals; no allocation anywhere)
__device__ __align__(16) float g_qkv[PP*768];            // fp32, attention input
__device__ __align__(16) __nv_bfloat16 xs_h[PP*256];     // x transposed+split
__device__ __align__(16) __nv_bfloat16 xs_l[PP*256];
__device__ __align__(16) __nv_bfloat16 g_aoh[PP*256];    // attention out planes
__device__ __align__(16) __nv_bfloat16 g_aol[PP*256];
__device__ __align__(16) __nv_bfloat16 g_inth[PP*256];   // bn1 out planes
__device__ __align__(16) __nv_bfloat16 g_intl[PP*256];
__device__ __align__(16) __nv_bfloat16 g_h1h[PP*256];    // ffn mid planes
__device__ __align__(16) __nv_bfloat16 g_h1l[PP*256];
__device__ __align__(16) __nv_bfloat16 wsp_h[WTOT];      // weights [out][in]
__device__ __align__(16) __nv_bfloat16 wsp_l[WTOT];

// ---------------------------------------------------------------------------
__device__ __forceinline__ void cp16(void* dst, const void* src) {
    unsigned int d = (unsigned int)__cvta_generic_to_shared(dst);
    asm volatile("cp.async.cg.shared.global [%0], [%1], 16;\n" :: "r"(d), "l"(src));
}
#define CP_COMMIT() asm volatile("cp.async.commit_group;\n" ::: "memory")
#define CP_WAIT1()  asm volatile("cp.async.wait_group 1;\n" ::: "memory")
#define CP_WAIT0()  asm volatile("cp.async.wait_group 0;\n" ::: "memory")

#define MMA_BF16(c, a0, a1, a2, a3, b0, b1) \
    asm volatile("mma.sync.aligned.m16n8k16.row.col.f32.bf16.bf16.f32 " \
        "{%0,%1,%2,%3}, {%4,%5,%6,%7}, {%8,%9}, {%0,%1,%2,%3};" \
        : "+f"((c)[0]), "+f"((c)[1]), "+f"((c)[2]), "+f"((c)[3]) \
        : "r"(a0), "r"(a1), "r"(a2), "r"(a3), "r"(b0), "r"(b1))

__device__ __forceinline__ void store_split2(__nv_bfloat16* dh, __nv_bfloat16* dl,
                                             size_t o, float v0, float v1) {
    __nv_bfloat16 h0 = __float2bfloat16_rn(v0);
    __nv_bfloat16 h1 = __float2bfloat16_rn(v1);
    __nv_bfloat162 hp; hp.x = h0; hp.y = h1;
    __nv_bfloat162 lp;
    lp.x = __float2bfloat16_rn(v0 - __bfloat162float(h0));
    lp.y = __float2bfloat16_rn(v1 - __bfloat162float(h1));
    *(__nv_bfloat162*)&dh[o] = hp;
    *(__nv_bfloat162*)&dl[o] = lp;
}
__device__ __forceinline__ float2 load_split2(const __nv_bfloat16* dh,
                                              const __nv_bfloat16* dl, size_t o) {
    __nv_bfloat162 h = *(const __nv_bfloat162*)&dh[o];
    __nv_bfloat162 l = *(const __nv_bfloat162*)&dl[o];
    return make_float2(__bfloat162float(h.x) + __bfloat162float(l.x),
                       __bfloat162float(h.y) + __bfloat162float(l.y));
}
// pack 4 floats -> hi uint2 / lo uint2 (4 bf16 each)
__device__ __forceinline__ void pack4(float4 f, uint2& hp, uint2& lp) {
    __nv_bfloat16 h0 = __float2bfloat16_rn(f.x), h1 = __float2bfloat16_rn(f.y);
    __nv_bfloat16 h2 = __float2bfloat16_rn(f.z), h3 = __float2bfloat16_rn(f.w);
    __nv_bfloat162 a; a.x = h0; a.y = h1;
    __nv_bfloat162 b; b.x = h2; b.y = h3;
    hp.x = *(uint32_t*)&a; hp.y = *(uint32_t*)&b;
    __nv_bfloat162 c = __floats2bfloat162_rn(f.x - __bfloat162float(h0),
                                             f.y - __bfloat162float(h1));
    __nv_bfloat162 d = __floats2bfloat162_rn(f.z - __bfloat162float(h2),
                                             f.w - __bfloat162float(h3));
    lp.x = *(uint32_t*)&c; lp.y = *(uint32_t*)&d;
}

// ---------------------------------------------------------------------------
// prep_w / prep_x (unchanged from round 8)
// ---------------------------------------------------------------------------
__global__ __launch_bounds__(256) void prep_w(const float* __restrict__ wq,
                                              const float* __restrict__ wo,
                                              const float* __restrict__ w1,
                                              const float* __restrict__ w2)
{
    int idx = blockIdx.x * 256 + threadIdx.x;
    if (idx >= WTOT) return;
    float v;
    if (idx < WO_OFF)      { int j = idx >> 8, k = idx & 255; v = wq[k*768 + j]; }
    else if (idx < W1_OFF) { int l = idx - WO_OFF; int j = l >> 8, k = l & 255; v = wo[k*256 + j]; }
    else if (idx < W2_OFF) { v = w1[idx - W1_OFF]; }
    else                   { v = w2[idx - W2_OFF]; }
    __nv_bfloat16 h = __float2bfloat16_rn(v);
    wsp_h[idx] = h;
    wsp_l[idx] = __float2bfloat16_rn(v - __bfloat162float(h));
}

#define PXSMEM (2*64*264*2)   // 67584 bytes
__global__ __launch_bounds__(256) void prep_x(const float* __restrict__ x)
{
    extern __shared__ __nv_bfloat16 sx[];
    __nv_bfloat16* sh = sx;
    __nv_bfloat16* sl = sx + 64*264;
    const int tid = threadIdx.x;
    const int p0 = blockIdx.x * 64;
    #pragma unroll 4
    for (int it = 0; it < 64; ++it) {
        int lin = it * 256 + tid;
        int pl = lin & 63, cl = lin >> 6;
        int p = p0 + pl;
        int n = p / TV, r = p - n * TV;
        float v = x[(size_t)(n*CC + cl)*TV + r];
        __nv_bfloat16 h = __float2bfloat16_rn(v);
        sh[pl*264 + cl] = h;
        sl[pl*264 + cl] = __float2bfloat16_rn(v - __bfloat162float(h));
    }
    __syncthreads();
    #pragma unroll
    for (int s = tid; s < 2048; s += 256) {
        int pl = s >> 5, seg = s & 31;
        *(uint4*)&xs_h[(size_t)(p0+pl)*256 + seg*8] = *(uint4*)&sh[pl*264 + seg*8];
        *(uint4*)&xs_l[(size_t)(p0+pl)*256 + seg*8] = *(uint4*)&sl[pl*264 + seg*8];
    }
}

// ---------------------------------------------------------------------------
// mma_gemm (unchanged from round 8)
// ---------------------------------------------------------------------------
#define GSTG 20480
#define GSMEM (2*GSTG*2)

template<int MODE>
__global__ __launch_bounds__(256)
void mma_gemm(const float* __restrict__ bias,
              const float* __restrict__ bg, const float* __restrict__ bb,
              const float* __restrict__ bm, const float* __restrict__ bv,
              float* __restrict__ outp)
{
    extern __shared__ __nv_bfloat16 smb[];

    const int tid  = threadIdx.x;
    const int lane = tid & 31;
    const int wid  = tid >> 5;
    const int wm   = wid >> 2;
    const int wn   = wid & 3;
    const int p0   = blockIdx.x * 128;
    const int jb   = blockIdx.y * 128;

    const __nv_bfloat16* Asrc_h;
    const __nv_bfloat16* Asrc_l;
    int woff;
    if constexpr (MODE == 0) { Asrc_h = xs_h;   Asrc_l = xs_l;   woff = WQ_OFF; }
    else if constexpr (MODE == 1) { Asrc_h = g_aoh;  Asrc_l = g_aol;  woff = WO_OFF; }
    else if constexpr (MODE == 2) { Asrc_h = g_inth; Asrc_l = g_intl; woff = W1_OFF; }
    else { Asrc_h = g_h1h; Asrc_l = g_h1l; woff = W2_OFF; }

    float acc[4][4][4];
    #pragma unroll
    for (int mi = 0; mi < 4; ++mi)
        #pragma unroll
        for (int ni = 0; ni < 4; ++ni)
            #pragma unroll
            for (int q = 0; q < 4; ++q) acc[mi][ni][q] = 0.f;

    auto fill = [&](int c, int st) {
        const int c0 = c * 32;
        __nv_bfloat16* Sg = smb + st * GSTG;
        #pragma unroll
        for (int i = 0; i < 8; ++i) {
            int s = i * 256 + tid;
            int plane = s >> 9;
            int e = s & 511;
            int row = e >> 2, sg = e & 3;
            const __nv_bfloat16* src;
            if (plane == 0) {
                int p = p0 + row; if (p >= PP) p = PP - 1;
                src = &Asrc_h[(size_t)p*256 + c0 + sg*8];
            } else if (plane == 1) {
                int p = p0 + row; if (p >= PP) p = PP - 1;
                src = &Asrc_l[(size_t)p*256 + c0 + sg*8];
            } else if (plane == 2) {
                src = &wsp_h[(size_t)woff + (size_t)(jb + row)*256 + c0 + sg*8];
            } else {
                src = &wsp_l[(size_t)woff + (size_t)(jb + row)*256 + c0 + sg*8];
            }
            cp16(&Sg[plane*5120 + row*40 + sg*8], src);
        }
    };

    auto compute = [&](int st) {
        const __nv_bfloat16* Ah = smb + st * GSTG;
        const __nv_bfloat16* Al = Ah + 5120;
        const __nv_bfloat16* Bh = Ah + 10240;
        const __nv_bfloat16* Bl = Ah + 15360;
        const int fr = lane >> 2;
        const int fc = (lane & 3) * 2;
        #pragma unroll
        for (int kh = 0; kh < 2; ++kh) {
            const int ko = kh * 16;
            uint32_t bh[4][2], bl[4][2];
            #pragma unroll
            for (int ni = 0; ni < 4; ++ni) {
                const __nv_bfloat16* pb = &Bh[(wn*32 + ni*8 + fr)*40 + ko + fc];
                bh[ni][0] = *(const uint32_t*)pb;
                bh[ni][1] = *(const uint32_t*)(pb + 8);
                const __nv_bfloat16* ql = &Bl[(wn*32 + ni*8 + fr)*40 + ko + fc];
                bl[ni][0] = *(const uint32_t*)ql;
                bl[ni][1] = *(const uint32_t*)(ql + 8);
            }
            #pragma unroll
            for (int mi = 0; mi < 4; ++mi) {
                const int ar = wm*64 + mi*16 + fr;
                const __nv_bfloat16* pa = &Ah[ar*40 + ko + fc];
                uint32_t ah0 = *(const uint32_t*)pa;
                uint32_t ah1 = *(const uint32_t*)(pa + 8*40);
                uint32_t ah2 = *(const uint32_t*)(pa + 8);
                uint32_t ah3 = *(const uint32_t*)(pa + 8*40 + 8);
                const __nv_bfloat16* qa = &Al[ar*40 + ko + fc];
                uint32_t al0 = *(const uint32_t*)qa;
                uint32_t al1 = *(const uint32_t*)(qa + 8*40);
                uint32_t al2 = *(const uint32_t*)(qa + 8);
                uint32_t al3 = *(const uint32_t*)(qa + 8*40 + 8);
                #pragma unroll
                for (int ni = 0; ni < 4; ++ni) {
                    MMA_BF16(acc[mi][ni], ah0, ah1, ah2, ah3, bh[ni][0], bh[ni][1]);
                    MMA_BF16(acc[mi][ni], ah0, ah1, ah2, ah3, bl[ni][0], bl[ni][1]);
                    MMA_BF16(acc[mi][ni], al0, al1, al2, al3, bh[ni][0], bh[ni][1]);
                }
            }
        }
    };

    fill(0, 0); CP_COMMIT();
    int st = 0;
    #pragma unroll 1
    for (int c = 0; c < 8; ++c) {
        if (c < 7) { fill(c + 1, st ^ 1); CP_COMMIT(); CP_WAIT1(); }
        else       { CP_WAIT0(); }
        __syncthreads();
        compute(st);
        __syncthreads();
        st ^= 1;
    }

    const int fr = lane >> 2;
    const int fc = (lane & 3) * 2;

    if constexpr (MODE == 0) {
        #pragma unroll
        for (int mi = 0; mi < 4; ++mi) {
            int pr = p0 + wm*64 + mi*16 + fr;
            #pragma unroll
            for (int ni = 0; ni < 4; ++ni) {
                int jc = jb + wn*32 + ni*8 + fc;
                if (pr < PP)
                    *(float2*)&g_qkv[(size_t)pr*768 + jc] =
                        make_float2(acc[mi][ni][0], acc[mi][ni][1]);
                if (pr + 8 < PP)
                    *(float2*)&g_qkv[(size_t)(pr+8)*768 + jc] =
                        make_float2(acc[mi][ni][2], acc[mi][ni][3]);
            }
        }
        return;
    }

    float sc[4][2], be[4][2], bo[4][2];
    #pragma unroll
    for (int ni = 0; ni < 4; ++ni)
        #pragma unroll
        for (int q = 0; q < 2; ++q) {
            int j = jb + wn*32 + ni*8 + fc + q;
            float s = rsqrtf(bv[j] + EPSV) * bg[j];
            sc[ni][q] = s;
            be[ni][q] = bb[j] - bm[j] * s;
            bo[ni][q] = (MODE == 1) ? bias[j] : 0.f;
        }

    if constexpr (MODE == 1) {
        #pragma unroll
        for (int mi = 0; mi < 4; ++mi) {
            int pr = p0 + wm*64 + mi*16 + fr;
            #pragma unroll
            for (int ni = 0; ni < 4; ++ni) {
                int jc = jb + wn*32 + ni*8 + fc;
                if (pr < PP) {
                    size_t o = (size_t)pr*256 + jc;
                    float2 xr = load_split2(xs_h, xs_l, o);
                    float v0 = (acc[mi][ni][0] + bo[ni][0] + xr.x)*sc[ni][0] + be[ni][0];
                    float v1 = (acc[mi][ni][1] + bo[ni][1] + xr.y)*sc[ni][1] + be[ni][1];
                    store_split2(g_inth, g_intl, o, v0, v1);
                }
                if (pr + 8 < PP) {
                    size_t o = (size_t)(pr+8)*256 + jc;
                    float2 xr = load_split2(xs_h, xs_l, o);
                    float v2 = (acc[mi][ni][2] + bo[ni][0] + xr.x)*sc[ni][0] + be[ni][0];
                    float v3 = (acc[mi][ni][3] + bo[ni][1] + xr.y)*sc[ni][1] + be[ni][1];
                    store_split2(g_inth, g_intl, o, v2, v3);
                }
            }
        }
        return;
    }

    if constexpr (MODE == 2) {
        #pragma unroll
        for (int mi = 0; mi < 4; ++mi) {
            int pr = p0 + wm*64 + mi*16 + fr;
            #pragma unroll
            for (int ni = 0; ni < 4; ++ni) {
                int jc = jb + wn*32 + ni*8 + fc;
                float v[4];
                #pragma unroll
                for (int q = 0; q < 4; ++q) {
                    float a = acc[mi][ni][q];
                    float sp = (a > 20.f) ? a : log1pf(__expf(a));
                    v[q] = a * tanhf(sp) * sc[ni][q & 1] + be[ni][q & 1];
                }
                if (pr < PP)
                    store_split2(g_h1h, g_h1l, (size_t)pr*256 + jc, v[0], v[1]);
                if (pr + 8 < PP)
                    store_split2(g_h1h, g_h1l, (size_t)(pr+8)*256 + jc, v[2], v[3]);
            }
        }
        return;
    }

    float* stg = (float*)smb;
    #pragma unroll 1
    for (int ph = 0; ph < 2; ++ph) {
        __syncthreads();
        if (wm == ph) {
            #pragma unroll
            for (int mi = 0; mi < 4; ++mi) {
                int lr = mi*16 + fr;
                int pr = p0 + ph*64 + lr;
                int p0c = (pr < PP) ? pr : PP - 1;
                int p1c = (pr + 8 < PP) ? pr + 8 : PP - 1;
                #pragma unroll
                for (int ni = 0; ni < 4; ++ni) {
                    int jl = wn*32 + ni*8 + fc;
                    float2 r0 = load_split2(g_inth, g_intl, (size_t)p0c*256 + jb + jl);
                    float2 r1 = load_split2(g_inth, g_intl, (size_t)p1c*256 + jb + jl);
                    stg[lr*132 + jl]       = (acc[mi][ni][0] + r0.x)*sc[ni][0] + be[ni][0];
                    stg[lr*132 + jl + 1]   = (acc[mi][ni][1] + r0.y)*sc[ni][1] + be[ni][1];
                    stg[(lr+8)*132 + jl]   = (acc[mi][ni][2] + r1.x)*sc[ni][0] + be[ni][0];
                    stg[(lr+8)*132 + jl+1] = (acc[mi][ni][3] + r1.y)*sc[ni][1] + be[ni][1];
                }
            }
        }
        __syncthreads();
        for (int idx = tid; idx < 64 * 128; idx += 256) {
            int pl = idx & 63, j = idx >> 6;
            int p = p0 + ph*64 + pl;
            if (p < PP) {
                int n = p / TV, r = p - n * TV;
                outp[(size_t)(n * CC + jb + j) * TV + r] = stg[pl*132 + j];
            }
        }
    }
}

// ---------------------------------------------------------------------------
// Attention v5: QK on tensor cores (bf16 2-term split mma.sync).
// smem (floats): S [125][132] @0 (bf16 QK planes overlay its first 40960 B,
// dead before S written), V @16500 [128][32], sums @20596, Sb @20724 [25][132].
// Total 24024 floats = 96096 B -> 2 CTAs/SM.
// ---------------------------------------------------------------------------
#define AT_V    16500
#define AT_SUM  20596
#define AT_SB   20724
#define ATTN_SMEM_FLOATS 24024

__global__ __launch_bounds__(256, 2)
void attn_kernel()
{
    extern __shared__ float smA[];
    float* S    = smA;
    float* vs   = smA + AT_V;
    float* sums = smA + AT_SUM;
    float* Sb   = smA + AT_SB;
    __nv_bfloat16* Qh = (__nv_bfloat16*)smA;          // 128 x 40
    __nv_bfloat16* Ql = Qh + 5120;
    __nv_bfloat16* Kh = Qh + 10240;
    __nv_bfloat16* Kl = Qh + 15360;

    const int tid  = threadIdx.x;
    const int lane = tid & 31;
    const int wid  = tid >> 5;
    const int wm   = wid >> 2;
    const int wn   = wid & 3;
    const int bx = blockIdx.x, h = blockIdx.y;
    const int n = bx / TT, t = bx - n * TT;

    // ---- phase 1: gather Q/K (split to bf16 planes) and V (fp32) ----
    for (int lin = tid; lin < 2000; lin += 256) {
        int m = lin >> 4;                // 0..124
        int c = lin & 15;                // q: 0-7, k: 8-15
        int w = m / VVC, vv = m - w * VVC;
        int ti = t + w - 2;
        float4 f = make_float4(0.f, 0.f, 0.f, 0.f);
        if (ti >= 0 && ti < TT)
            f = *(const float4*)&g_qkv[((size_t)((n*TT + ti)*VVC + vv))*768 + h*96 + c*4];
        uint2 hp, lp;
        pack4(f, hp, lp);
        int d0 = (c & 7) * 4;
        __nv_bfloat16* dh = (c < 8) ? Qh : Kh;
        __nv_bfloat16* dl = (c < 8) ? Ql : Kl;
        *(uint2*)&dh[m*40 + d0] = hp;
        *(uint2*)&dl[m*40 + d0] = lp;
    }
    for (int lin = tid; lin < 1000; lin += 256) {
        int m = lin >> 3, c = lin & 7;
        int w = m / VVC, vv = m - w * VVC;
        int ti = t + w - 2;
        float4 f = make_float4(0.f, 0.f, 0.f, 0.f);
        if (ti >= 0 && ti < TT)
            f = *(const float4*)&g_qkv[((size_t)((n*TT + ti)*VVC + vv))*768 + h*96 + 64 + c*4];
        *(float4*)&vs[m*32 + c*4] = f;
    }
    if (tid < 96) {                      // zero pad rows 125..127
        int m = 125 + (tid >> 5), d = tid & 31;
        Qh[m*40 + d] = __float2bfloat16(0.f);
        Ql[m*40 + d] = __float2bfloat16(0.f);
        Kh[m*40 + d] = __float2bfloat16(0.f);
        Kl[m*40 + d] = __float2bfloat16(0.f);
        vs[m*32 + d] = 0.f;
    }
    __syncthreads();

    // ---- phase 2: S = Q K^T (tensor cores, 3-MMA split) ----
    float acc[4][4][4];
    #pragma unroll
    for (int mi = 0; mi < 4; ++mi)
        #pragma unroll
        for (int ni = 0; ni < 4; ++ni)
            #pragma unroll
            for (int q = 0; q < 4; ++q) acc[mi][ni][q] = 0.f;

    const int fr = lane >> 2;
    const int fc = (lane & 3) * 2;
    #pragma unroll
    for (int kh = 0; kh < 2; ++kh) {
        const int ko = kh * 16;
        uint32_t bh[4][2], bl[4][2];
        #pragma unroll
        for (int ni = 0; ni < 4; ++ni) {
            const __nv_bfloat16* pb = &Kh[(wn*32 + ni*8 + fr)*40 + ko + fc];
            bh[ni][0] = *(const uint32_t*)pb;
            bh[ni][1] = *(const uint32_t*)(pb + 8);
            const __nv_bfloat16* ql = &Kl[(wn*32 + ni*8 + fr)*40 + ko + fc];
            bl[ni][0] = *(const uint32_t*)ql;
            bl[ni][1] = *(const uint32_t*)(ql + 8);
        }
        #pragma unroll
        for (int mi = 0; mi < 4; ++mi) {
            const int ar = wm*64 + mi*16 + fr;
            const __nv_bfloat16* pa = &Qh[ar*40 + ko + fc];
            uint32_t ah0 = *(const uint32_t*)pa;
            uint32_t ah1 = *(const uint32_t*)(pa + 8*40);
            uint32_t ah2 = *(const uint32_t*)(pa + 8);
            uint32_t ah3 = *(const uint32_t*)(pa + 8*40 + 8);
            const __nv_bfloat16* qa = &Ql[ar*40 + ko + fc];
            uint32_t al0 = *(const uint32_t*)qa;
            uint32_t al1 = *(const uint32_t*)(qa + 8*40);
            uint32_t al2 = *(const uint32_t*)(qa + 8);
            uint32_t al3 = *(const uint32_t*)(qa + 8*40 + 8);
            #pragma unroll
            for (int ni = 0; ni < 4; ++ni) {
                MMA_BF16(acc[mi][ni], ah0, ah1, ah2, ah3, bh[ni][0], bh[ni][1]);
                MMA_BF16(acc[mi][ni], ah0, ah1, ah2, ah3, bl[ni][0], bl[ni][1]);
                MMA_BF16(acc[mi][ni], al0, al1, al2, al3, bh[ni][0], bh[ni][1]);
            }
        }
    }
    __syncthreads();   // QK planes dead; safe to overlay S

    // ---- phase 3: write S (scale 1/16, mask cols >= 125 to -inf) ----
    #pragma unroll
    for (int mi = 0; mi < 4; ++mi) {
        int r0 = wm*64 + mi*16 + fr;
        int r1 = r0 + 8;
        #pragma unroll
        for (int ni = 0; ni < 4; ++ni) {
            int jc = wn*32 + ni*8 + fc;
            float v0 = (jc     >= LLN) ? -1e30f : acc[mi][ni][0] * 0.0625f;
            float v1 = (jc + 1 >= LLN) ? -1e30f : acc[mi][ni][1] * 0.0625f;
            float v2 = (jc     >= LLN) ? -1e30f : acc[mi][ni][2] * 0.0625f;
            float v3 = (jc + 1 >= LLN) ? -1e30f : acc[mi][ni][3] * 0.0625f;
            if (r0 < LLN) *(float2*)&S[r0*132 + jc] = make_float2(v0, v1);
            if (r1 < LLN) *(float2*)&S[r1*132 + jc] = make_float2(v2, v3);
        }
    }
    __syncthreads();

    // ---- phase 4: single-pass softmax (no max; scores are small) ----
    if (tid < LLN) {
        const int l = tid;
        float4* row = (float4*)&S[l*132];
        float s = 0.f;
        #pragma unroll
        for (int i = 0; i < 32; ++i) {
            float4 f = row[i];
            f.x = __expf(f.x); f.y = __expf(f.y);
            f.z = __expf(f.z); f.w = __expf(f.w);
            s += f.x + f.y + f.z + f.w;
            row[i] = f;
        }
        sums[l] = 0.2f / s;
    }
    __syncthreads();

    // ---- phase 5: S-bar[v] = sum_w S[(w,v)] * (0.2/sum_w) ----
    for (int task = tid; task < 25*32; task += 256) {
        int v = task >> 5, i4 = task & 31;
        float4 r = make_float4(0.f, 0.f, 0.f, 0.f);
        #pragma unroll
        for (int w = 0; w < 5; ++w) {
            int l = w*VVC + v;
            float rs = sums[l];
            float4 f = *(const float4*)&S[l*132 + i4*4];
            r.x = fmaf(f.x, rs, r.x); r.y = fmaf(f.y, rs, r.y);
            r.z = fmaf(f.z, rs, r.z); r.w = fmaf(f.w, rs, r.w);
        }
        *(float4*)&Sb[v*132 + i4*4] = r;
    }
    __syncthreads();

    // ---- phase 6: O = S-bar @ V (25 x 32), split-write g_ao planes ----
    if (tid < 200) {
        const int v = tid >> 3, g = tid & 7;
        float4 a4 = make_float4(0.f, 0.f, 0.f, 0.f);
        #pragma unroll 8
        for (int m = 0; m < 128; ++m) {
            float a = Sb[v*132 + m];
            float4 b = *(const float4*)&vs[m*32 + g*4];
            a4.x = fmaf(a, b.x, a4.x); a4.y = fmaf(a, b.y, a4.y);
            a4.z = fmaf(a, b.z, a4.z); a4.w = fmaf(a, b.w, a4.w);
        }
        size_t base = ((size_t)((n*TT + t)*VVC + v))*256 + h*HD + g*4;
        store_split2(g_aoh, g_aol, base,     a4.x, a4.y);
        store_split2(g_aoh, g_aol, base + 2, a4.z, a4.w);
    }
}

// ---------------------------------------------------------------------------
extern "C" void kernel_launch(void* const* d_in, const int* in_sizes, int n_in,
                              void* d_out, int out_size)
{
    const float* x      = (const float*)d_in[0];
    const float* w_qkv  = (const float*)d_in[1];
    const float* w_out  = (const float*)d_in[2];
    const float* b_out  = (const float*)d_in[3];
    const float* bn1_g  = (const float*)d_in[4];
    const float* bn1_b  = (const float*)d_in[5];
    const float* ffn_w1 = (const float*)d_in[6];
    const float* ffn_w2 = (const float*)d_in[7];
    const float* ffn_g  = (const float*)d_in[8];
    const float* ffn_b  = (const float*)d_in[9];
    const float* bn2_g  = (const float*)d_in[10];
    const float* bn2_b  = (const float*)d_in[11];
    const float* bn1_m  = (const float*)d_in[12];
    const float* bn1_v  = (const float*)d_in[13];
    const float* ffn_m  = (const float*)d_in[14];
    const float* ffn_v  = (const float*)d_in[15];
    const float* bn2_m  = (const float*)d_in[16];
    const float* bn2_v  = (const float*)d_in[17];
    float* out = (float*)d_out;

    static int attr_done = 0;
    if (!attr_done) {
        cudaFuncSetAttribute(attn_kernel,
            cudaFuncAttributeMaxDynamicSharedMemorySize, ATTN_SMEM_FLOATS * 4);
        cudaFuncSetAttribute(prep_x,
            cudaFuncAttributeMaxDynamicSharedMemorySize, PXSMEM);
        cudaFuncSetAttribute(mma_gemm<0>,
            cudaFuncAttributeMaxDynamicSharedMemorySize, GSMEM);
        cudaFuncSetAttribute(mma_gemm<1>,
            cudaFuncAttributeMaxDynamicSharedMemorySize, GSMEM);
        cudaFuncSetAttribute(mma_gemm<2>,
            cudaFuncAttributeMaxDynamicSharedMemorySize, GSMEM);
        cudaFuncSetAttribute(mma_gemm<3>,
            cudaFuncAttributeMaxDynamicSharedMemorySize, GSMEM);
        attr_done = 1;
    }

    const int MT = (PP + 127) / 128;   // 188 M-tiles

    prep_w<<<(WTOT + 255)/256, 256>>>(w_qkv, w_out, ffn_w1, ffn_w2);
    prep_x<<<PP/64, 256, PXSMEM>>>(x);

    mma_gemm<0><<<dim3(MT, 6), 256, GSMEM>>>(
        nullptr, nullptr, nullptr, nullptr, nullptr, nullptr);

    attn_kernel<<<dim3(NB*TT, HH), 256, ATTN_SMEM_FLOATS * 4>>>();

    mma_gemm<1><<<dim3(MT, 2), 256, GSMEM>>>(
        b_out, bn1_g, bn1_b, bn1_m, bn1_v, nullptr);

    mma_gemm<2><<<dim3(MT, 2), 256, GSMEM>>>(
        nullptr, ffn_g, ffn_b, ffn_m, ffn_v, nullptr);

    mma_gemm<3><<<dim3(MT, 2), 256, GSMEM>>>(
        nullptr, bn2_g, bn2_b, bn2_m, bn2_v, out);
}

// round 10
// speedup vs baseline: 2.5022x; 1.0649x over previous
#include <cuda_runtime.h>
#include <cuda_bf16.h>
#include <cstdint>
#include <math.h>

#define NB 8
#define CC 256
#define TT 120
#define VVC 25
#define PP (NB*TT*VVC)   // 24000 points
#define TV (TT*VVC)      // 3000
#define HH 8
#define HD 32
#define LLN 125
#define EPSV 1e-5f

#define WQ_OFF 0
#define WO_OFF 196608
#define W1_OFF 262144
#define W2_OFF 327680
#define WTOT   393216

// Scratch (device globals; no allocation anywhere)
__device__ __align__(16) float g_qkv[PP*768];            // fp32, attention input
__device__ __align__(16) __nv_bfloat16 xs_h[PP*256];     // x transposed+split
__device__ __align__(16) __nv_bfloat16 xs_l[PP*256];
__device__ __align__(16) __nv_bfloat16 g_aoh[PP*256];    // attention out planes
__device__ __align__(16) __nv_bfloat16 g_aol[PP*256];
__device__ __align__(16) __nv_bfloat16 g_inth[PP*256];   // bn1 out planes
__device__ __align__(16) __nv_bfloat16 g_intl[PP*256];
__device__ __align__(16) __nv_bfloat16 g_h1h[PP*256];    // ffn mid planes
__device__ __align__(16) __nv_bfloat16 g_h1l[PP*256];
__device__ __align__(16) __nv_bfloat16 wsp_h[WTOT];      // weights [out][in]
__device__ __align__(16) __nv_bfloat16 wsp_l[WTOT];

// ---------------------------------------------------------------------------
__device__ __forceinline__ void cp16(void* dst, const void* src) {
    unsigned int d = (unsigned int)__cvta_generic_to_shared(dst);
    asm volatile("cp.async.cg.shared.global [%0], [%1], 16;\n" :: "r"(d), "l"(src));
}
#define CP_COMMIT() asm volatile("cp.async.commit_group;\n" ::: "memory")
#define CP_WAIT1()  asm volatile("cp.async.wait_group 1;\n" ::: "memory")
#define CP_WAIT0()  asm volatile("cp.async.wait_group 0;\n" ::: "memory")

#define MMA_BF16(c, a0, a1, a2, a3, b0, b1) \
    asm volatile("mma.sync.aligned.m16n8k16.row.col.f32.bf16.bf16.f32 " \
        "{%0,%1,%2,%3}, {%4,%5,%6,%7}, {%8,%9}, {%0,%1,%2,%3};" \
        : "+f"((c)[0]), "+f"((c)[1]), "+f"((c)[2]), "+f"((c)[3]) \
        : "r"(a0), "r"(a1), "r"(a2), "r"(a3), "r"(b0), "r"(b1))

__device__ __forceinline__ void store_split2(__nv_bfloat16* dh, __nv_bfloat16* dl,
                                             size_t o, float v0, float v1) {
    __nv_bfloat16 h0 = __float2bfloat16_rn(v0);
    __nv_bfloat16 h1 = __float2bfloat16_rn(v1);
    __nv_bfloat162 hp; hp.x = h0; hp.y = h1;
    __nv_bfloat162 lp;
    lp.x = __float2bfloat16_rn(v0 - __bfloat162float(h0));
    lp.y = __float2bfloat16_rn(v1 - __bfloat162float(h1));
    *(__nv_bfloat162*)&dh[o] = hp;
    *(__nv_bfloat162*)&dl[o] = lp;
}
__device__ __forceinline__ float2 load_split2(const __nv_bfloat16* dh,
                                              const __nv_bfloat16* dl, size_t o) {
    __nv_bfloat162 h = *(const __nv_bfloat162*)&dh[o];
    __nv_bfloat162 l = *(const __nv_bfloat162*)&dl[o];
    return make_float2(__bfloat162float(h.x) + __bfloat162float(l.x),
                       __bfloat162float(h.y) + __bfloat162float(l.y));
}
// pack 4 floats -> hi uint2 / lo uint2 (4 bf16 each)
__device__ __forceinline__ void pack4(float4 f, uint2& hp, uint2& lp) {
    __nv_bfloat16 h0 = __float2bfloat16_rn(f.x), h1 = __float2bfloat16_rn(f.y);
    __nv_bfloat16 h2 = __float2bfloat16_rn(f.z), h3 = __float2bfloat16_rn(f.w);
    __nv_bfloat162 a; a.x = h0; a.y = h1;
    __nv_bfloat162 b; b.x = h2; b.y = h3;
    hp.x = *(uint32_t*)&a; hp.y = *(uint32_t*)&b;
    __nv_bfloat162 c = __floats2bfloat162_rn(f.x - __bfloat162float(h0),
                                             f.y - __bfloat162float(h1));
    __nv_bfloat162 d = __floats2bfloat162_rn(f.z - __bfloat162float(h2),
                                             f.w - __bfloat162float(h3));
    lp.x = *(uint32_t*)&c; lp.y = *(uint32_t*)&d;
}

// ---------------------------------------------------------------------------
// prep_w / prep_x (unchanged)
// ---------------------------------------------------------------------------
__global__ __launch_bounds__(256) void prep_w(const float* __restrict__ wq,
                                              const float* __restrict__ wo,
                                              const float* __restrict__ w1,
                                              const float* __restrict__ w2)
{
    int idx = blockIdx.x * 256 + threadIdx.x;
    if (idx >= WTOT) return;
    float v;
    if (idx < WO_OFF)      { int j = idx >> 8, k = idx & 255; v = wq[k*768 + j]; }
    else if (idx < W1_OFF) { int l = idx - WO_OFF; int j = l >> 8, k = l & 255; v = wo[k*256 + j]; }
    else if (idx < W2_OFF) { v = w1[idx - W1_OFF]; }
    else                   { v = w2[idx - W2_OFF]; }
    __nv_bfloat16 h = __float2bfloat16_rn(v);
    wsp_h[idx] = h;
    wsp_l[idx] = __float2bfloat16_rn(v - __bfloat162float(h));
}

#define PXSMEM (2*64*264*2)   // 67584 bytes
__global__ __launch_bounds__(256) void prep_x(const float* __restrict__ x)
{
    extern __shared__ __nv_bfloat16 sx[];
    __nv_bfloat16* sh = sx;
    __nv_bfloat16* sl = sx + 64*264;
    const int tid = threadIdx.x;
    const int p0 = blockIdx.x * 64;
    #pragma unroll 4
    for (int it = 0; it < 64; ++it) {
        int lin = it * 256 + tid;
        int pl = lin & 63, cl = lin >> 6;
        int p = p0 + pl;
        int n = p / TV, r = p - n * TV;
        float v = x[(size_t)(n*CC + cl)*TV + r];
        __nv_bfloat16 h = __float2bfloat16_rn(v);
        sh[pl*264 + cl] = h;
        sl[pl*264 + cl] = __float2bfloat16_rn(v - __bfloat162float(h));
    }
    __syncthreads();
    #pragma unroll
    for (int s = tid; s < 2048; s += 256) {
        int pl = s >> 5, seg = s & 31;
        *(uint4*)&xs_h[(size_t)(p0+pl)*256 + seg*8] = *(uint4*)&sh[pl*264 + seg*8];
        *(uint4*)&xs_l[(size_t)(p0+pl)*256 + seg*8] = *(uint4*)&sl[pl*264 + seg*8];
    }
}

// ---------------------------------------------------------------------------
// mma_gemm (unchanged from round 9)
// ---------------------------------------------------------------------------
#define GSTG 20480
#define GSMEM (2*GSTG*2)

template<int MODE>
__global__ __launch_bounds__(256)
void mma_gemm(const float* __restrict__ bias,
              const float* __restrict__ bg, const float* __restrict__ bb,
              const float* __restrict__ bm, const float* __restrict__ bv,
              float* __restrict__ outp)
{
    extern __shared__ __nv_bfloat16 smb[];

    const int tid  = threadIdx.x;
    const int lane = tid & 31;
    const int wid  = tid >> 5;
    const int wm   = wid >> 2;
    const int wn   = wid & 3;
    const int p0   = blockIdx.x * 128;
    const int jb   = blockIdx.y * 128;

    const __nv_bfloat16* Asrc_h;
    const __nv_bfloat16* Asrc_l;
    int woff;
    if constexpr (MODE == 0) { Asrc_h = xs_h;   Asrc_l = xs_l;   woff = WQ_OFF; }
    else if constexpr (MODE == 1) { Asrc_h = g_aoh;  Asrc_l = g_aol;  woff = WO_OFF; }
    else if constexpr (MODE == 2) { Asrc_h = g_inth; Asrc_l = g_intl; woff = W1_OFF; }
    else { Asrc_h = g_h1h; Asrc_l = g_h1l; woff = W2_OFF; }

    float acc[4][4][4];
    #pragma unroll
    for (int mi = 0; mi < 4; ++mi)
        #pragma unroll
        for (int ni = 0; ni < 4; ++ni)
            #pragma unroll
            for (int q = 0; q < 4; ++q) acc[mi][ni][q] = 0.f;

    auto fill = [&](int c, int st) {
        const int c0 = c * 32;
        __nv_bfloat16* Sg = smb + st * GSTG;
        #pragma unroll
        for (int i = 0; i < 8; ++i) {
            int s = i * 256 + tid;
            int plane = s >> 9;
            int e = s & 511;
            int row = e >> 2, sg = e & 3;
            const __nv_bfloat16* src;
            if (plane == 0) {
                int p = p0 + row; if (p >= PP) p = PP - 1;
                src = &Asrc_h[(size_t)p*256 + c0 + sg*8];
            } else if (plane == 1) {
                int p = p0 + row; if (p >= PP) p = PP - 1;
                src = &Asrc_l[(size_t)p*256 + c0 + sg*8];
            } else if (plane == 2) {
                src = &wsp_h[(size_t)woff + (size_t)(jb + row)*256 + c0 + sg*8];
            } else {
                src = &wsp_l[(size_t)woff + (size_t)(jb + row)*256 + c0 + sg*8];
            }
            cp16(&Sg[plane*5120 + row*40 + sg*8], src);
        }
    };

    auto compute = [&](int st) {
        const __nv_bfloat16* Ah = smb + st * GSTG;
        const __nv_bfloat16* Al = Ah + 5120;
        const __nv_bfloat16* Bh = Ah + 10240;
        const __nv_bfloat16* Bl = Ah + 15360;
        const int fr = lane >> 2;
        const int fc = (lane & 3) * 2;
        #pragma unroll
        for (int kh = 0; kh < 2; ++kh) {
            const int ko = kh * 16;
            uint32_t bh[4][2], bl[4][2];
            #pragma unroll
            for (int ni = 0; ni < 4; ++ni) {
                const __nv_bfloat16* pb = &Bh[(wn*32 + ni*8 + fr)*40 + ko + fc];
                bh[ni][0] = *(const uint32_t*)pb;
                bh[ni][1] = *(const uint32_t*)(pb + 8);
                const __nv_bfloat16* ql = &Bl[(wn*32 + ni*8 + fr)*40 + ko + fc];
                bl[ni][0] = *(const uint32_t*)ql;
                bl[ni][1] = *(const uint32_t*)(ql + 8);
            }
            #pragma unroll
            for (int mi = 0; mi < 4; ++mi) {
                const int ar = wm*64 + mi*16 + fr;
                const __nv_bfloat16* pa = &Ah[ar*40 + ko + fc];
                uint32_t ah0 = *(const uint32_t*)pa;
                uint32_t ah1 = *(const uint32_t*)(pa + 8*40);
                uint32_t ah2 = *(const uint32_t*)(pa + 8);
                uint32_t ah3 = *(const uint32_t*)(pa + 8*40 + 8);
                const __nv_bfloat16* qa = &Al[ar*40 + ko + fc];
                uint32_t al0 = *(const uint32_t*)qa;
                uint32_t al1 = *(const uint32_t*)(qa + 8*40);
                uint32_t al2 = *(const uint32_t*)(qa + 8);
                uint32_t al3 = *(const uint32_t*)(qa + 8*40 + 8);
                #pragma unroll
                for (int ni = 0; ni < 4; ++ni) {
                    MMA_BF16(acc[mi][ni], ah0, ah1, ah2, ah3, bh[ni][0], bh[ni][1]);
                    MMA_BF16(acc[mi][ni], ah0, ah1, ah2, ah3, bl[ni][0], bl[ni][1]);
                    MMA_BF16(acc[mi][ni], al0, al1, al2, al3, bh[ni][0], bh[ni][1]);
                }
            }
        }
    };

    fill(0, 0); CP_COMMIT();
    int st = 0;
    #pragma unroll 1
    for (int c = 0; c < 8; ++c) {
        if (c < 7) { fill(c + 1, st ^ 1); CP_COMMIT(); CP_WAIT1(); }
        else       { CP_WAIT0(); }
        __syncthreads();
        compute(st);
        __syncthreads();
        st ^= 1;
    }

    const int fr = lane >> 2;
    const int fc = (lane & 3) * 2;

    if constexpr (MODE == 0) {
        #pragma unroll
        for (int mi = 0; mi < 4; ++mi) {
            int pr = p0 + wm*64 + mi*16 + fr;
            #pragma unroll
            for (int ni = 0; ni < 4; ++ni) {
                int jc = jb + wn*32 + ni*8 + fc;
                if (pr < PP)
                    *(float2*)&g_qkv[(size_t)pr*768 + jc] =
                        make_float2(acc[mi][ni][0], acc[mi][ni][1]);
                if (pr + 8 < PP)
                    *(float2*)&g_qkv[(size_t)(pr+8)*768 + jc] =
                        make_float2(acc[mi][ni][2], acc[mi][ni][3]);
            }
        }
        return;
    }

    float sc[4][2], be[4][2], bo[4][2];
    #pragma unroll
    for (int ni = 0; ni < 4; ++ni)
        #pragma unroll
        for (int q = 0; q < 2; ++q) {
            int j = jb + wn*32 + ni*8 + fc + q;
            float s = rsqrtf(bv[j] + EPSV) * bg[j];
            sc[ni][q] = s;
            be[ni][q] = bb[j] - bm[j] * s;
            bo[ni][q] = (MODE == 1) ? bias[j] : 0.f;
        }

    if constexpr (MODE == 1) {
        #pragma unroll
        for (int mi = 0; mi < 4; ++mi) {
            int pr = p0 + wm*64 + mi*16 + fr;
            #pragma unroll
            for (int ni = 0; ni < 4; ++ni) {
                int jc = jb + wn*32 + ni*8 + fc;
                if (pr < PP) {
                    size_t o = (size_t)pr*256 + jc;
                    float2 xr = load_split2(xs_h, xs_l, o);
                    float v0 = (acc[mi][ni][0] + bo[ni][0] + xr.x)*sc[ni][0] + be[ni][0];
                    float v1 = (acc[mi][ni][1] + bo[ni][1] + xr.y)*sc[ni][1] + be[ni][1];
                    store_split2(g_inth, g_intl, o, v0, v1);
                }
                if (pr + 8 < PP) {
                    size_t o = (size_t)(pr+8)*256 + jc;
                    float2 xr = load_split2(xs_h, xs_l, o);
                    float v2 = (acc[mi][ni][2] + bo[ni][0] + xr.x)*sc[ni][0] + be[ni][0];
                    float v3 = (acc[mi][ni][3] + bo[ni][1] + xr.y)*sc[ni][1] + be[ni][1];
                    store_split2(g_inth, g_intl, o, v2, v3);
                }
            }
        }
        return;
    }

    if constexpr (MODE == 2) {
        #pragma unroll
        for (int mi = 0; mi < 4; ++mi) {
            int pr = p0 + wm*64 + mi*16 + fr;
            #pragma unroll
            for (int ni = 0; ni < 4; ++ni) {
                int jc = jb + wn*32 + ni*8 + fc;
                float v[4];
                #pragma unroll
                for (int q = 0; q < 4; ++q) {
                    float a = acc[mi][ni][q];
                    float sp = (a > 20.f) ? a : log1pf(__expf(a));
                    v[q] = a * tanhf(sp) * sc[ni][q & 1] + be[ni][q & 1];
                }
                if (pr < PP)
                    store_split2(g_h1h, g_h1l, (size_t)pr*256 + jc, v[0], v[1]);
                if (pr + 8 < PP)
                    store_split2(g_h1h, g_h1l, (size_t)(pr+8)*256 + jc, v[2], v[3]);
            }
        }
        return;
    }

    float* stg = (float*)smb;
    #pragma unroll 1
    for (int ph = 0; ph < 2; ++ph) {
        __syncthreads();
        if (wm == ph) {
            #pragma unroll
            for (int mi = 0; mi < 4; ++mi) {
                int lr = mi*16 + fr;
                int pr = p0 + ph*64 + lr;
                int p0c = (pr < PP) ? pr : PP - 1;
                int p1c = (pr + 8 < PP) ? pr + 8 : PP - 1;
                #pragma unroll
                for (int ni = 0; ni < 4; ++ni) {
                    int jl = wn*32 + ni*8 + fc;
                    float2 r0 = load_split2(g_inth, g_intl, (size_t)p0c*256 + jb + jl);
                    float2 r1 = load_split2(g_inth, g_intl, (size_t)p1c*256 + jb + jl);
                    stg[lr*132 + jl]       = (acc[mi][ni][0] + r0.x)*sc[ni][0] + be[ni][0];
                    stg[lr*132 + jl + 1]   = (acc[mi][ni][1] + r0.y)*sc[ni][1] + be[ni][1];
                    stg[(lr+8)*132 + jl]   = (acc[mi][ni][2] + r1.x)*sc[ni][0] + be[ni][0];
                    stg[(lr+8)*132 + jl+1] = (acc[mi][ni][3] + r1.y)*sc[ni][1] + be[ni][1];
                }
            }
        }
        __syncthreads();
        for (int idx = tid; idx < 64 * 128; idx += 256) {
            int pl = idx & 63, j = idx >> 6;
            int p = p0 + ph*64 + pl;
            if (p < PP) {
                int n = p / TV, r = p - n * TV;
                outp[(size_t)(n * CC + jb + j) * TV + r] = stg[pl*132 + j];
            }
        }
    }
}

// ---------------------------------------------------------------------------
// Attention v6: full tensor-core path.
// QK MMA -> exp in registers -> P bf16 hi/lo planes (+row sums via shfl) ->
// SV MMA (T = P.V, V stored transposed [d][m] as bf16 planes) -> tiny O pass.
// smem (bf16-element offsets unless noted):
//   P region @0: Ph[128][136] @0, Pl @17408 (QK planes Qh/Ql/Kh/Kl, stride 40,
//     overlay @0/5120/10240/15360 during phases 1-2; dead before P write)
//   Vh @34816 [32][136], Vl @39168
//   T (float idx) @21760: [128][36] fp32
//   sums2d (float idx) @26368: [4][128];  sums @26880: [128]
// Total 27008 floats = 108032 B -> 2 CTAs/SM.
// ---------------------------------------------------------------------------
#define AT_PL   17408
#define AT_VH   34816
#define AT_VL   39168
#define AT_T    21760
#define AT_S2D  26368
#define AT_SUM  26880
#define ATTN_SMEM_FLOATS 27008

__global__ __launch_bounds__(256, 2)
void attn_kernel()
{
    extern __shared__ float smA[];
    __nv_bfloat16* bb_ = (__nv_bfloat16*)smA;
    __nv_bfloat16* Qh = bb_;                 // stride 40
    __nv_bfloat16* Ql = bb_ + 5120;
    __nv_bfloat16* Kh = bb_ + 10240;
    __nv_bfloat16* Kl = bb_ + 15360;
    __nv_bfloat16* Ph = bb_;                 // stride 136 (overlays QK planes)
    __nv_bfloat16* Pl = bb_ + AT_PL;
    __nv_bfloat16* Vh = bb_ + AT_VH;         // [d][m], stride 136
    __nv_bfloat16* Vl = bb_ + AT_VL;
    float* T    = smA + AT_T;                // [128][36]
    float* s2d  = smA + AT_S2D;              // [4][128]
    float* sums = smA + AT_SUM;

    const int tid  = threadIdx.x;
    const int lane = tid & 31;
    const int wid  = tid >> 5;
    const int wm   = wid >> 2;
    const int wn   = wid & 3;
    const int bx = blockIdx.x, h = blockIdx.y;
    const int n = bx / TT, t = bx - n * TT;
    const int fr = lane >> 2;
    const int fc = (lane & 3) * 2;

    // ---- phase 1: gather Q/K planes (stride 40) + V transposed planes ----
    for (int lin = tid; lin < 2000; lin += 256) {
        int m = lin >> 4;
        int c = lin & 15;                    // q: 0-7, k: 8-15
        int w = m / VVC, vv = m - w * VVC;
        int ti = t + w - 2;
        float4 f = make_float4(0.f, 0.f, 0.f, 0.f);
        if (ti >= 0 && ti < TT)
            f = *(const float4*)&g_qkv[((size_t)((n*TT + ti)*VVC + vv))*768 + h*96 + c*4];
        uint2 hp, lp;
        pack4(f, hp, lp);
        int d0 = (c & 7) * 4;
        __nv_bfloat16* dh = (c < 8) ? Qh : Kh;
        __nv_bfloat16* dl = (c < 8) ? Ql : Kl;
        *(uint2*)&dh[m*40 + d0] = hp;
        *(uint2*)&dl[m*40 + d0] = lp;
    }
    for (int lin = tid; lin < 1000; lin += 256) {
        int m = lin >> 3, c = lin & 7;
        int w = m / VVC, vv = m - w * VVC;
        int ti = t + w - 2;
        float4 f = make_float4(0.f, 0.f, 0.f, 0.f);
        if (ti >= 0 && ti < TT)
            f = *(const float4*)&g_qkv[((size_t)((n*TT + ti)*VVC + vv))*768 + h*96 + 64 + c*4];
        // transposed store: V[d][m]
        int d0 = c * 4;
        float vv4[4] = {f.x, f.y, f.z, f.w};
        #pragma unroll
        for (int j = 0; j < 4; ++j) {
            __nv_bfloat16 hv = __float2bfloat16_rn(vv4[j]);
            Vh[(d0 + j)*136 + m] = hv;
            Vl[(d0 + j)*136 + m] = __float2bfloat16_rn(vv4[j] - __bfloat162float(hv));
        }
    }
    if (tid < 96) {                          // zero pad rows/cols 125..127
        int m = 125 + (tid >> 5), d = tid & 31;
        __nv_bfloat16 z = __float2bfloat16(0.f);
        Qh[m*40 + d] = z; Ql[m*40 + d] = z;
        Kh[m*40 + d] = z; Kl[m*40 + d] = z;
        Vh[d*136 + m] = z; Vl[d*136 + m] = z;
    }
    __syncthreads();

    // ---- phase 2: S = Q K^T (tensor cores, 3-MMA split) ----
    float acc[4][4][4];
    #pragma unroll
    for (int mi = 0; mi < 4; ++mi)
        #pragma unroll
        for (int ni = 0; ni < 4; ++ni)
            #pragma unroll
            for (int q = 0; q < 4; ++q) acc[mi][ni][q] = 0.f;

    #pragma unroll
    for (int kh = 0; kh < 2; ++kh) {
        const int ko = kh * 16;
        uint32_t bh[4][2], bl[4][2];
        #pragma unroll
        for (int ni = 0; ni < 4; ++ni) {
            const __nv_bfloat16* pb = &Kh[(wn*32 + ni*8 + fr)*40 + ko + fc];
            bh[ni][0] = *(const uint32_t*)pb;
            bh[ni][1] = *(const uint32_t*)(pb + 8);
            const __nv_bfloat16* ql = &Kl[(wn*32 + ni*8 + fr)*40 + ko + fc];
            bl[ni][0] = *(const uint32_t*)ql;
            bl[ni][1] = *(const uint32_t*)(ql + 8);
        }
        #pragma unroll
        for (int mi = 0; mi < 4; ++mi) {
            const int ar = wm*64 + mi*16 + fr;
            const __nv_bfloat16* pa = &Qh[ar*40 + ko + fc];
            uint32_t ah0 = *(const uint32_t*)pa;
            uint32_t ah1 = *(const uint32_t*)(pa + 8*40);
            uint32_t ah2 = *(const uint32_t*)(pa + 8);
            uint32_t ah3 = *(const uint32_t*)(pa + 8*40 + 8);
            const __nv_bfloat16* qa = &Ql[ar*40 + ko + fc];
            uint32_t al0 = *(const uint32_t*)qa;
            uint32_t al1 = *(const uint32_t*)(qa + 8*40);
            uint32_t al2 = *(const uint32_t*)(qa + 8);
            uint32_t al3 = *(const uint32_t*)(qa + 8*40 + 8);
            #pragma unroll
            for (int ni = 0; ni < 4; ++ni) {
                MMA_BF16(acc[mi][ni], ah0, ah1, ah2, ah3, bh[ni][0], bh[ni][1]);
                MMA_BF16(acc[mi][ni], ah0, ah1, ah2, ah3, bl[ni][0], bl[ni][1]);
                MMA_BF16(acc[mi][ni], al0, al1, al2, al3, bh[ni][0], bh[ni][1]);
            }
        }
    }
    __syncthreads();   // QK planes dead; safe to overlay P

    // ---- phase 3: exp in registers -> P planes + row-sum partials ----
    #pragma unroll
    for (int mi = 0; mi < 4; ++mi) {
        int r0 = wm*64 + mi*16 + fr;
        int r1 = r0 + 8;
        float s0 = 0.f, s1 = 0.f;
        #pragma unroll
        for (int ni = 0; ni < 4; ++ni) {
            int jc = wn*32 + ni*8 + fc;
            float p0 = (jc     >= LLN) ? 0.f : __expf(acc[mi][ni][0] * 0.0625f);
            float p1 = (jc + 1 >= LLN) ? 0.f : __expf(acc[mi][ni][1] * 0.0625f);
            float p2 = (jc     >= LLN) ? 0.f : __expf(acc[mi][ni][2] * 0.0625f);
            float p3 = (jc + 1 >= LLN) ? 0.f : __expf(acc[mi][ni][3] * 0.0625f);
            store_split2(Ph, Pl, (size_t)r0*136 + jc, p0, p1);
            store_split2(Ph, Pl, (size_t)r1*136 + jc, p2, p3);
            s0 += p0 + p1;
            s1 += p2 + p3;
        }
        s0 += __shfl_xor_sync(0xffffffffu, s0, 1);
        s0 += __shfl_xor_sync(0xffffffffu, s0, 2);
        s1 += __shfl_xor_sync(0xffffffffu, s1, 1);
        s1 += __shfl_xor_sync(0xffffffffu, s1, 2);
        if ((lane & 3) == 0) {
            s2d[wn*128 + r0] = s0;
            s2d[wn*128 + r1] = s1;
        }
    }
    __syncthreads();

    // ---- phase 4: combine row sums (tid<125), then SV MMA: T = P.V ----
    if (tid < LLN)
        sums[tid] = 0.2f / (s2d[tid] + s2d[128 + tid] + s2d[256 + tid] + s2d[384 + tid]);

    float accS[4][4];
    #pragma unroll
    for (int ni = 0; ni < 4; ++ni)
        #pragma unroll
        for (int q = 0; q < 4; ++q) accS[ni][q] = 0.f;

    #pragma unroll
    for (int kh = 0; kh < 8; ++kh) {
        const int ko = kh * 16;
        uint32_t bh[4][2], bl[4][2];
        #pragma unroll
        for (int ni = 0; ni < 4; ++ni) {
            const __nv_bfloat16* pb = &Vh[(ni*8 + fr)*136 + ko + fc];
            bh[ni][0] = *(const uint32_t*)pb;
            bh[ni][1] = *(const uint32_t*)(pb + 8);
            const __nv_bfloat16* ql = &Vl[(ni*8 + fr)*136 + ko + fc];
            bl[ni][0] = *(const uint32_t*)ql;
            bl[ni][1] = *(const uint32_t*)(ql + 8);
        }
        const int ar = wid*16 + fr;
        const __nv_bfloat16* pa = &Ph[ar*136 + ko + fc];
        uint32_t ah0 = *(const uint32_t*)pa;
        uint32_t ah1 = *(const uint32_t*)(pa + 8*136);
        uint32_t ah2 = *(const uint32_t*)(pa + 8);
        uint32_t ah3 = *(const uint32_t*)(pa + 8*136 + 8);
        const __nv_bfloat16* qa = &Pl[ar*136 + ko + fc];
        uint32_t al0 = *(const uint32_t*)qa;
        uint32_t al1 = *(const uint32_t*)(qa + 8*136);
        uint32_t al2 = *(const uint32_t*)(qa + 8);
        uint32_t al3 = *(const uint32_t*)(qa + 8*136 + 8);
        #pragma unroll
        for (int ni = 0; ni < 4; ++ni) {
            MMA_BF16(accS[ni], ah0, ah1, ah2, ah3, bh[ni][0], bh[ni][1]);
            MMA_BF16(accS[ni], ah0, ah1, ah2, ah3, bl[ni][0], bl[ni][1]);
            MMA_BF16(accS[ni], al0, al1, al2, al3, bh[ni][0], bh[ni][1]);
        }
    }
    // write T
    #pragma unroll
    for (int ni = 0; ni < 4; ++ni) {
        int col = ni*8 + fc;
        int row = wid*16 + fr;
        *(float2*)&T[row*36 + col]     = make_float2(accS[ni][0], accS[ni][1]);
        *(float2*)&T[(row+8)*36 + col] = make_float2(accS[ni][2], accS[ni][3]);
    }
    __syncthreads();

    // ---- phase 5: O[v,d] = sum_w T[w*25+v,d] * (0.2/sum) -> g_ao planes ----
    if (tid < 200) {
        const int v = tid >> 3, g = tid & 7;
        float4 a4 = make_float4(0.f, 0.f, 0.f, 0.f);
        #pragma unroll
        for (int w = 0; w < 5; ++w) {
            int l = w*VVC + v;
            float rs = sums[l];
            float4 tv = *(const float4*)&T[l*36 + g*4];
            a4.x = fmaf(tv.x, rs, a4.x); a4.y = fmaf(tv.y, rs, a4.y);
            a4.z = fmaf(tv.z, rs, a4.z); a4.w = fmaf(tv.w, rs, a4.w);
        }
        size_t base = ((size_t)((n*TT + t)*VVC + v))*256 + h*HD + g*4;
        store_split2(g_aoh, g_aol, base,     a4.x, a4.y);
        store_split2(g_aoh, g_aol, base + 2, a4.z, a4.w);
    }
}

// ---------------------------------------------------------------------------
extern "C" void kernel_launch(void* const* d_in, const int* in_sizes, int n_in,
                              void* d_out, int out_size)
{
    const float* x      = (const float*)d_in[0];
    const float* w_qkv  = (const float*)d_in[1];
    const float* w_out  = (const float*)d_in[2];
    const float* b_out  = (const float*)d_in[3];
    const float* bn1_g  = (const float*)d_in[4];
    const float* bn1_b  = (const float*)d_in[5];
    const float* ffn_w1 = (const float*)d_in[6];
    const float* ffn_w2 = (const float*)d_in[7];
    const float* ffn_g  = (const float*)d_in[8];
    const float* ffn_b  = (const float*)d_in[9];
    const float* bn2_g  = (const float*)d_in[10];
    const float* bn2_b  = (const float*)d_in[11];
    const float* bn1_m  = (const float*)d_in[12];
    const float* bn1_v  = (const float*)d_in[13];
    const float* ffn_m  = (const float*)d_in[14];
    const float* ffn_v  = (const float*)d_in[15];
    const float* bn2_m  = (const float*)d_in[16];
    const float* bn2_v  = (const float*)d_in[17];
    float* out = (float*)d_out;

    static int attr_done = 0;
    if (!attr_done) {
        cudaFuncSetAttribute(attn_kernel,
            cudaFuncAttributeMaxDynamicSharedMemorySize, ATTN_SMEM_FLOATS * 4);
        cudaFuncSetAttribute(prep_x,
            cudaFuncAttributeMaxDynamicSharedMemorySize, PXSMEM);
        cudaFuncSetAttribute(mma_gemm<0>,
            cudaFuncAttributeMaxDynamicSharedMemorySize, GSMEM);
        cudaFuncSetAttribute(mma_gemm<1>,
            cudaFuncAttributeMaxDynamicSharedMemorySize, GSMEM);
        cudaFuncSetAttribute(mma_gemm<2>,
            cudaFuncAttributeMaxDynamicSharedMemorySize, GSMEM);
        cudaFuncSetAttribute(mma_gemm<3>,
            cudaFuncAttributeMaxDynamicSharedMemorySize, GSMEM);
        attr_done = 1;
    }

    const int MT = (PP + 127) / 128;   // 188 M-tiles

    prep_w<<<(WTOT + 255)/256, 256>>>(w_qkv, w_out, ffn_w1, ffn_w2);
    prep_x<<<PP/64, 256, PXSMEM>>>(x);

    mma_gemm<0><<<dim3(MT, 6), 256, GSMEM>>>(
        nullptr, nullptr, nullptr, nullptr, nullptr, nullptr);

    attn_kernel<<<dim3(NB*TT, HH), 256, ATTN_SMEM_FLOATS * 4>>>();

    mma_gemm<1><<<dim3(MT, 2), 256, GSMEM>>>(
        b_out, bn1_g, bn1_b, bn1_m, bn1_v, nullptr);

    mma_gemm<2><<<dim3(MT, 2), 256, GSMEM>>>(
        nullptr, ffn_g, ffn_b, ffn_m, ffn_v, nullptr);

    mma_gemm<3><<<dim3(MT, 2), 256, GSMEM>>>(
        nullptr, bn2_g, bn2_b, bn2_m, bn2_v, out);
}